// round 9
// baseline (speedup 1.0000x reference)
#include <cuda_runtime.h>
#include <cstdint>

// ===========================================================================
// SWIN attention layer on GB300 (sm_103 base target — NO tcgen05).
// All GEMM-like work on tensor pipe via mma.sync.m16n8k8.tf32 + ldmatrix.
// R9: 512-thread GEMM (4x4 warp grid, 3-buffer B ring, 1 sync/chunk),
//     512-thread attention (2 warps per head).
// ===========================================================================

namespace {
constexpr int TOK = 32 * 64 * 64;          // 131072 tokens
constexpr int MT  = TOK / 128;             // 1024 M-tiles
constexpr float SCALE = 0.17677669529663687f;
constexpr float NEGM  = -1e9f;
constexpr int AST = 36;                    // GEMM smem row stride (floats)
constexpr int CHUNK_B = 128 * AST * 4;     // 18432 B per [128][36] tile
constexpr int SMB_OFF = 8 * CHUNK_B;       // B ring after A chunks
constexpr int GSMEM   = 8 * CHUNK_B + 3 * CHUNK_B;   // 202752 B

// attention smem (floats)
constexpr int KS_OFF = 0;                          // [8][64][36]
constexpr int VT_OFF = KS_OFF + 8 * 64 * 36;       // [8][32][68]
constexpr int QP_OFF = VT_OFF + 8 * 32 * 68;       // [16 warps][16][68]
constexpr int ASMEM  = (QP_OFF + 16 * 16 * 68) * 4; // 212992 B
}

// static device scratch
__device__ float    g_qkv[(size_t)TOK * 768];
__device__ float    g_ao [(size_t)TOK * 256];
__device__ float    g_y  [(size_t)TOK * 256];
__device__ uint32_t g_wqkv_p[6 * 8 * 128 * AST];
__device__ uint32_t g_wo_p  [2 * 8 * 128 * AST];

__device__ __forceinline__ uint32_t smem_u32(const void* p) {
    uint32_t a;
    asm("{ .reg .u64 t; cvta.to.shared.u64 t, %1; cvt.u32.u64 %0, t; }"
        : "=r"(a) : "l"(p));
    return a;
}
__device__ __forceinline__ uint32_t f2tf32(float f) {
    uint32_t u;
    asm("cvt.rna.tf32.f32 %0, %1;" : "=r"(u) : "f"(f));
    return u;
}
__device__ __forceinline__ float f2tf32f(float f) {
    return __uint_as_float(f2tf32(f));
}
__device__ __forceinline__ void ldsm_x4(uint32_t* r, uint32_t a) {
    asm volatile("ldmatrix.sync.aligned.m8n8.x4.shared.b16 {%0,%1,%2,%3}, [%4];"
                 : "=r"(r[0]), "=r"(r[1]), "=r"(r[2]), "=r"(r[3]) : "r"(a));
}
__device__ __forceinline__ void mma_tf32(float* c, const uint32_t* a,
                                         uint32_t b0, uint32_t b1) {
    asm volatile(
        "mma.sync.aligned.m16n8k8.row.col.f32.tf32.tf32.f32 "
        "{%0,%1,%2,%3}, {%4,%5,%6,%7}, {%8,%9}, {%0,%1,%2,%3};"
        : "+f"(c[0]), "+f"(c[1]), "+f"(c[2]), "+f"(c[3])
        : "r"(a[0]), "r"(a[1]), "r"(a[2]), "r"(a[3]), "r"(b0), "r"(b1));
}

template <bool SHIFT>
__device__ __forceinline__ size_t tok_img_off(int T) {
    const int win = T >> 6, pos = T & 63;
    const int b = win >> 6, w = win & 63;
    int gr = (w >> 3) * 8 + (pos >> 3);
    int gc = (w & 7) * 8 + (pos & 7);
    if (SHIFT) { gr = (gr + 4) & 63; gc = (gc + 4) & 63; }
    return ((size_t)((b * 64 + gr) * 64 + gc)) * 256;
}
__device__ __forceinline__ int regid_of(int w, int pos) {
    const int gr = (w >> 3) * 8 + (pos >> 3);
    const int gc = (w & 7) * 8 + (pos & 7);
    const int rr = (gr < 56) ? 0 : (gr < 60 ? 1 : 2);
    const int cc = (gc < 56) ? 0 : (gc < 60 ? 1 : 2);
    return rr * 3 + cc;
}

// ---------------------------------------------------------------------------
// weight pre-pack (validated)
// ---------------------------------------------------------------------------
__global__ void prepack_w(const float* __restrict__ w, uint32_t* __restrict__ dst,
                          int NT)
{
    const int LDB = NT * 128;
    const int total = NT * 8 * 128 * 32;
    for (int idx = blockIdx.x * blockDim.x + threadIdx.x; idx < total;
         idx += gridDim.x * blockDim.x) {
        const int k   = idx & 31;
        const int n   = (idx >> 5) & 127;
        const int blk = idx >> 12;
        const int kc  = blk & 7, nt = blk >> 3;
        const float v = w[(size_t)(kc * 32 + k) * LDB + nt * 128 + n];
        dst[(size_t)(blk * 128 + n) * AST + k] = f2tf32(v);
    }
}

// ---------------------------------------------------------------------------
// tf32 mma.sync GEMM, 512 threads, 4x4 warp grid, 3-buffer B ring, 1 sync/chunk
// ---------------------------------------------------------------------------
template <int NT, bool LINEAR_A, bool LINEAR_OUT, bool SHIFT>
__global__ __launch_bounds__(512, 1)
void gemm_mma(const float* __restrict__ A, const uint32_t* __restrict__ Bp,
              const float* __restrict__ bias, float* __restrict__ Out)
{
    constexpr int LDB = NT * 128;
    extern __shared__ char smraw[];
    uint32_t* As = (uint32_t*)smraw;
    uint32_t* Bs = (uint32_t*)(smraw + SMB_OFF);
    const uint32_t smb = smem_u32(smraw);

    const int tid  = threadIdx.x;
    const int lane = tid & 31;
    const int wid  = tid >> 5;     // 0..15
    const int wm   = wid & 3;      // 32-row band
    const int wn   = wid >> 2;     // 32-col band
    const int mt   = blockIdx.x;

    // ---- A gather + tf32 convert (coalesced 64B runs per 4-lane group) ----
    {
        const int row = tid >> 2;
        const int T   = mt * 128 + row;
        const float* arow = LINEAR_A ? (A + (size_t)T * 256)
                                     : (A + tok_img_off<SHIFT>(T));
#pragma unroll
        for (int j = 0; j < 16; j++) {
            const int c4  = (tid & 3) + 4 * j;
            const float4 v = *((const float4*)arow + c4);
            const int col = c4 * 4;
            const int kc  = col >> 5, k = col & 31;
            uint4 u = { f2tf32(v.x), f2tf32(v.y), f2tf32(v.z), f2tf32(v.w) };
            *(uint4*)(As + (size_t)kc * (128 * AST) + row * AST + k) = u;
        }
    }

    const int a_row = (lane & 7) + ((lane >> 3) & 1) * 8;
    const int a_k   = ((lane >> 4) & 1) * 4;
    const int b_n   = (lane & 7);
    const int b_k   = (lane >> 3) * 4;

    float acc[2][4][4];
    const int total_cc = NT * 8;

    // ---- prologue: STS chunk0, prefetch chunk1 ----
    uint4 pf[3];
    {
#pragma unroll
        for (int j = 0; j < 3; j++) {
            const int i = tid + j * 512;
            if (i < 1152) ((uint4*)Bs)[i] = ((const uint4*)Bp)[i];
        }
        if (total_cc > 1) {
            const uint4* src = (const uint4*)(Bp + (size_t)(128 * AST));
#pragma unroll
            for (int j = 0; j < 3; j++) {
                const int i = tid + j * 512;
                if (i < 1152) pf[j] = src[i];
            }
        }
    }
    __syncthreads();

    for (int cc = 0; cc < total_cc; cc++) {
        const int nt  = cc >> 3;
        const int kc  = cc & 7;
        const int buf = cc % 3;

        if (kc == 0) {
#pragma unroll
            for (int mi = 0; mi < 2; mi++)
#pragma unroll
                for (int ni = 0; ni < 4; ni++)
#pragma unroll
                    for (int e = 0; e < 4; e++) acc[mi][ni][e] = 0.f;
        }

        // STS chunk cc+1 into ring (its buffer was last read at chunk cc-2)
        if (cc + 1 < total_cc) {
            uint32_t* dstb = Bs + (size_t)((cc + 1) % 3) * (128 * AST);
#pragma unroll
            for (int j = 0; j < 3; j++) {
                const int i = tid + j * 512;
                if (i < 1152) ((uint4*)dstb)[i] = pf[j];
            }
        }
        // LDG prefetch chunk cc+2
        if (cc + 2 < total_cc) {
            const uint4* src = (const uint4*)(Bp + (size_t)(cc + 2) * (128 * AST));
#pragma unroll
            for (int j = 0; j < 3; j++) {
                const int i = tid + j * 512;
                if (i < 1152) pf[j] = src[i];
            }
        }

        // ---- compute chunk cc ----
        const uint32_t a_base = smb + kc * CHUNK_B + ((wm * 32 + a_row) * AST) * 4;
        const uint32_t b_base = smb + SMB_OFF + buf * CHUNK_B
                              + ((wn * 32 + b_n) * AST) * 4;
#pragma unroll
        for (int kp = 0; kp < 2; kp++) {
            uint32_t bf[4][4];
#pragma unroll
            for (int ni = 0; ni < 4; ni++)
                ldsm_x4(bf[ni], b_base + (ni * 8) * AST * 4 + (kp * 16 + b_k) * 4);
#pragma unroll
            for (int half = 0; half < 2; half++) {
                const int ks = kp * 2 + half;
                uint32_t af[2][4];
#pragma unroll
                for (int mi = 0; mi < 2; mi++)
                    ldsm_x4(af[mi], a_base + (mi * 16) * AST * 4 + (ks * 8 + a_k) * 4);
#pragma unroll
                for (int mi = 0; mi < 2; mi++)
#pragma unroll
                    for (int ni = 0; ni < 4; ni++)
                        mma_tf32(acc[mi][ni], af[mi],
                                 bf[ni][half * 2], bf[ni][half * 2 + 1]);
            }
        }

        // ---- epilogue at the end of each n-tile ----
        if (kc == 7) {
            const int g  = lane >> 2, tg = lane & 3;
            const int nb = nt * 128 + wn * 32;
#pragma unroll
            for (int mi = 0; mi < 2; mi++) {
#pragma unroll
                for (int hr = 0; hr < 2; hr++) {
                    const int T = mt * 128 + wm * 32 + mi * 16 + g + hr * 8;
                    float* orow = LINEAR_OUT ? (Out + (size_t)T * LDB)
                                             : (Out + tok_img_off<SHIFT>(T));
#pragma unroll
                    for (int ni = 0; ni < 4; ni++) {
                        const int c = nb + ni * 8 + 2 * tg;
                        float2 v;
                        v.x = acc[mi][ni][hr * 2]     + bias[c];
                        v.y = acc[mi][ni][hr * 2 + 1] + bias[c + 1];
                        *(float2*)(orow + c) = v;
                    }
                }
            }
        }
        __syncthreads();   // readers done with buf[cc%3]; STS of buf[(cc+1)%3] visible
    }
}

// ---------------------------------------------------------------------------
// tensor-core attention, 512 threads: 2 warps per head, each owns 2 q-blocks.
// ---------------------------------------------------------------------------
template <bool MASKED>
__global__ __launch_bounds__(512, 1)
void attn_mma(const float* __restrict__ qkv, float* __restrict__ ao)
{
    extern __shared__ char smraw[];
    float* smf = (float*)smraw;
    const int t    = threadIdx.x;
    const int lane = t & 31;
    const int wid  = t >> 5;       // 0..15
    const int h    = wid >> 1;     // head
    const int sub  = wid & 1;      // half within head
    const int win  = blockIdx.x;
    const int w    = win & 63;
    const size_t Tb = (size_t)win * 64;

    float* ks = smf + KS_OFF + h * (64 * 36);
    float* vt = smf + VT_OFF + h * (32 * 68);
    float* qp = smf + QP_OFF + wid * (16 * 68);   // per-warp Q/P/O buffer

    const float* hb = qkv + Tb * 768 + h * 32;

    // ---- stage K and V^T (each warp stages its half of tokens) ----
#pragma unroll
    for (int j = 0; j < 8; j++) {
        const int tok = sub * 32 + j * 4 + (lane >> 3);
        const int d4  = lane & 7;
        const float4 kv = *(const float4*)(hb + (size_t)tok * 768 + 256 + d4 * 4);
        uint4 u = { f2tf32(kv.x), f2tf32(kv.y), f2tf32(kv.z), f2tf32(kv.w) };
        *(uint4*)(ks + tok * 36 + d4 * 4) = u;
        const float4 vv = *(const float4*)(hb + (size_t)tok * 768 + 512 + d4 * 4);
        const int db = d4 * 4;
        vt[(db + 0) * 68 + tok] = f2tf32f(vv.x);
        vt[(db + 1) * 68 + tok] = f2tf32f(vv.y);
        vt[(db + 2) * 68 + tok] = f2tf32f(vv.z);
        vt[(db + 3) * 68 + tok] = f2tf32f(vv.w);
    }

    const int g  = lane >> 2, tg = lane & 3;
    const int a_row = (lane & 7) + ((lane >> 3) & 1) * 8;
    const int a_k   = ((lane >> 4) & 1) * 4;
    const int b_n   = lane & 7;
    const int b_k   = (lane >> 3) * 4;

    const uint32_t qp_lm = smem_u32(qp) + (a_row * 68) * 4;
    const uint32_t ks_lm = smem_u32(ks) + (b_n * 36) * 4;
    const uint32_t vt_lm = smem_u32(vt) + (b_n * 68) * 4;

    int rid_c[16];
    if (MASKED) {
#pragma unroll
        for (int ni = 0; ni < 8; ni++) {
            rid_c[ni * 2]     = regid_of(w, ni * 8 + 2 * tg);
            rid_c[ni * 2 + 1] = regid_of(w, ni * 8 + 2 * tg + 1);
        }
    }
    __syncthreads();   // K/V staged by both warps of each head

    for (int ml = 0; ml < 2; ml++) {
        const int mi = sub * 2 + ml;   // q-block 0..3
        // ---- Q block [16][32] into qp (stride 68) ----
#pragma unroll
        for (int it = 0; it < 4; it++) {
            const int row = it * 4 + (lane >> 3);
            const int d4  = lane & 7;
            const float4 qv =
                *(const float4*)(hb + (size_t)(mi * 16 + row) * 768 + d4 * 4);
            uint4 u = { f2tf32(qv.x), f2tf32(qv.y), f2tf32(qv.z), f2tf32(qv.w) };
            *(uint4*)(qp + row * 68 + d4 * 4) = u;
        }
        __syncwarp();

        // ---- S = Q K^T : s[8 n-tiles][4] ----
        float s[8][4];
#pragma unroll
        for (int ni = 0; ni < 8; ni++)
#pragma unroll
            for (int e = 0; e < 4; e++) s[ni][e] = 0.f;
#pragma unroll
        for (int kp = 0; kp < 2; kp++) {
            uint32_t bf[8][4];
#pragma unroll
            for (int ni = 0; ni < 8; ni++)
                ldsm_x4(bf[ni], ks_lm + (ni * 8) * 36 * 4 + (kp * 16 + b_k) * 4);
#pragma unroll
            for (int half = 0; half < 2; half++) {
                const int ksx = kp * 2 + half;
                uint32_t af[4];
                ldsm_x4(af, qp_lm + (ksx * 8 + a_k) * 4);
#pragma unroll
                for (int ni = 0; ni < 8; ni++)
                    mma_tf32(s[ni], af, bf[ni][half * 2], bf[ni][half * 2 + 1]);
            }
        }

        // ---- scale + mask ----
        int r0 = 0, r1 = 0;
        if (MASKED) {
            r0 = regid_of(w, mi * 16 + g);
            r1 = regid_of(w, mi * 16 + g + 8);
        }
#pragma unroll
        for (int ni = 0; ni < 8; ni++) {
#pragma unroll
            for (int e = 0; e < 2; e++) {
                s[ni][e]     = s[ni][e] * SCALE
                             + ((MASKED && r0 != rid_c[ni * 2 + e]) ? NEGM : 0.f);
                s[ni][2 + e] = s[ni][2 + e] * SCALE
                             + ((MASKED && r1 != rid_c[ni * 2 + e]) ? NEGM : 0.f);
            }
        }

        // ---- softmax (rows g, g+8; 4 lanes per row) ----
        float m0 = -3.0e38f, m1 = -3.0e38f;
#pragma unroll
        for (int ni = 0; ni < 8; ni++) {
            m0 = fmaxf(m0, fmaxf(s[ni][0], s[ni][1]));
            m1 = fmaxf(m1, fmaxf(s[ni][2], s[ni][3]));
        }
        m0 = fmaxf(m0, __shfl_xor_sync(0xffffffffu, m0, 1));
        m0 = fmaxf(m0, __shfl_xor_sync(0xffffffffu, m0, 2));
        m1 = fmaxf(m1, __shfl_xor_sync(0xffffffffu, m1, 1));
        m1 = fmaxf(m1, __shfl_xor_sync(0xffffffffu, m1, 2));
        float sum0 = 0.f, sum1 = 0.f;
#pragma unroll
        for (int ni = 0; ni < 8; ni++) {
            s[ni][0] = __expf(s[ni][0] - m0); sum0 += s[ni][0];
            s[ni][1] = __expf(s[ni][1] - m0); sum0 += s[ni][1];
            s[ni][2] = __expf(s[ni][2] - m1); sum1 += s[ni][2];
            s[ni][3] = __expf(s[ni][3] - m1); sum1 += s[ni][3];
        }
        sum0 += __shfl_xor_sync(0xffffffffu, sum0, 1);
        sum0 += __shfl_xor_sync(0xffffffffu, sum0, 2);
        sum1 += __shfl_xor_sync(0xffffffffu, sum1, 1);
        sum1 += __shfl_xor_sync(0xffffffffu, sum1, 2);
        const float i0 = 1.0f / sum0, i1 = 1.0f / sum1;

        // ---- P (tf32) -> qp (Q is dead now) ----
        __syncwarp();
#pragma unroll
        for (int ni = 0; ni < 8; ni++) {
            float2 p0 = { f2tf32f(s[ni][0] * i0), f2tf32f(s[ni][1] * i0) };
            float2 p1 = { f2tf32f(s[ni][2] * i1), f2tf32f(s[ni][3] * i1) };
            *(float2*)(qp + g * 68 + ni * 8 + 2 * tg)       = p0;
            *(float2*)(qp + (g + 8) * 68 + ni * 8 + 2 * tg) = p1;
        }
        __syncwarp();

        // ---- O = P @ V : o[4][4] ----
        float o[4][4];
#pragma unroll
        for (int ni = 0; ni < 4; ni++)
#pragma unroll
            for (int e = 0; e < 4; e++) o[ni][e] = 0.f;
#pragma unroll
        for (int kp = 0; kp < 4; kp++) {
            uint32_t bf2[4][4];
#pragma unroll
            for (int ni = 0; ni < 4; ni++)
                ldsm_x4(bf2[ni], vt_lm + (ni * 8) * 68 * 4 + (kp * 16 + b_k) * 4);
#pragma unroll
            for (int half = 0; half < 2; half++) {
                const int ksx = kp * 2 + half;
                uint32_t af[4];
                ldsm_x4(af, qp_lm + (ksx * 8 + a_k) * 4);
#pragma unroll
                for (int ni = 0; ni < 4; ni++)
                    mma_tf32(o[ni], af, bf2[ni][half * 2], bf2[ni][half * 2 + 1]);
            }
        }
        __syncwarp();   // qp reads done; reuse for O staging

        // ---- stage O, then coalesced 128B writes ----
#pragma unroll
        for (int ni = 0; ni < 4; ni++) {
            *(float2*)(qp + g * 68 + ni * 8 + 2 * tg)       = make_float2(o[ni][0], o[ni][1]);
            *(float2*)(qp + (g + 8) * 68 + ni * 8 + 2 * tg) = make_float2(o[ni][2], o[ni][3]);
        }
        __syncwarp();
#pragma unroll
        for (int it = 0; it < 4; it++) {
            const int row = it * 4 + (lane >> 3);
            const int c4  = lane & 7;
            const float4 vv = *(const float4*)(qp + row * 68 + c4 * 4);
            *(float4*)(ao + (Tb + mi * 16 + row) * 256 + h * 32 + c4 * 4) = vv;
        }
        __syncwarp();   // before next ml overwrites qp
    }
}

// ---------------------------------------------------------------------------
extern "C" void kernel_launch(void* const* d_in, const int* in_sizes, int n_in,
                              void* d_out, int out_size)
{
    const float* x    = (const float*)d_in[0];
    const float* wqkv = (const float*)d_in[1];
    const float* bqkv = (const float*)d_in[2];
    const float* wo   = (const float*)d_in[3];
    const float* bo   = (const float*)d_in[4];
    float* out = (float*)d_out;

    float *qkv_p, *ao_p, *y_p;
    uint32_t *wq_p, *wo_pk;
    cudaGetSymbolAddress((void**)&qkv_p, g_qkv);
    cudaGetSymbolAddress((void**)&ao_p,  g_ao);
    cudaGetSymbolAddress((void**)&y_p,   g_y);
    cudaGetSymbolAddress((void**)&wq_p,  g_wqkv_p);
    cudaGetSymbolAddress((void**)&wo_pk, g_wo_p);

    cudaFuncSetAttribute(gemm_mma<6, false, true,  false>,
                         cudaFuncAttributeMaxDynamicSharedMemorySize, GSMEM);
    cudaFuncSetAttribute(gemm_mma<6, false, true,  true>,
                         cudaFuncAttributeMaxDynamicSharedMemorySize, GSMEM);
    cudaFuncSetAttribute(gemm_mma<2, true,  false, false>,
                         cudaFuncAttributeMaxDynamicSharedMemorySize, GSMEM);
    cudaFuncSetAttribute(gemm_mma<2, true,  false, true>,
                         cudaFuncAttributeMaxDynamicSharedMemorySize, GSMEM);
    cudaFuncSetAttribute(attn_mma<false>,
                         cudaFuncAttributeMaxDynamicSharedMemorySize, ASMEM);
    cudaFuncSetAttribute(attn_mma<true>,
                         cudaFuncAttributeMaxDynamicSharedMemorySize, ASMEM);

    prepack_w<<<192, 256>>>(wqkv, wq_p, 6);
    prepack_w<<<64,  256>>>(wo,   wo_pk, 2);

    // pass 1 (unshifted)
    gemm_mma<6, false, true,  false><<<MT, 512, GSMEM>>>(x,    wq_p,  bqkv, qkv_p);
    attn_mma<false><<<2048, 512, ASMEM>>>(qkv_p, ao_p);
    gemm_mma<2, true,  false, false><<<MT, 512, GSMEM>>>(ao_p, wo_pk, bo,   y_p);
    // pass 2 (shifted + mask)
    gemm_mma<6, false, true,  true ><<<MT, 512, GSMEM>>>(y_p,  wq_p,  bqkv, qkv_p);
    attn_mma<true><<<2048, 512, ASMEM>>>(qkv_p, ao_p);
    gemm_mma<2, true,  false, true ><<<MT, 512, GSMEM>>>(ao_p, wo_pk, bo,   out);
}

// round 10
// speedup vs baseline: 1.5905x; 1.5905x over previous
#include <cuda_runtime.h>
#include <cstdint>

// ===========================================================================
// SWIN attention layer on GB300 (sm_103 base target — NO tcgen05).
// R10: qkv GEMM (R8-validated, 256 thr) -> fused attention+output-proj kernel.
// mma.sync.m16n8k8.tf32 + ldmatrix throughout.
// ===========================================================================

namespace {
constexpr int TOK = 32 * 64 * 64;          // 131072 tokens
constexpr int MT  = TOK / 128;             // 1024 M-tiles
constexpr float SCALE = 0.17677669529663687f;
constexpr float NEGM  = -1e9f;
constexpr int AST = 36;                    // smem row stride (floats)
constexpr int CHUNK_B = 128 * AST * 4;     // 18432 B per [128][36] tile
constexpr int GSMEM = 8 * CHUNK_B + 2 * CHUNK_B;   // 184320 B

// fused attn+proj smem layout (floats)
constexpr int QS_OFF = 0;                          // [8][16][36]   Q staging
constexpr int KS_OFF = QS_OFF + 8 * 16 * 36;       // [8][64][36]   K, then ao chunks
constexpr int VT_OFF = KS_OFF + 8 * 64 * 36;       // [8][32][68]   V^T, then Wo ring
constexpr int PB_OFF = VT_OFF + 8 * 32 * 68;       // [8][16][68]   P staging
constexpr int ASMEM  = (PB_OFF + 8 * 16 * 68) * 4; // 196608 B
constexpr int AO_CH  = 64 * AST;                   // floats per ao chunk
}

// static device scratch
__device__ float    g_qkv[(size_t)TOK * 768];
__device__ float    g_y  [(size_t)TOK * 256];
__device__ uint32_t g_wqkv_p[6 * 8 * 128 * AST];
__device__ uint32_t g_wo_p  [2 * 8 * 128 * AST];

__device__ __forceinline__ uint32_t smem_u32(const void* p) {
    uint32_t a;
    asm("{ .reg .u64 t; cvta.to.shared.u64 t, %1; cvt.u32.u64 %0, t; }"
        : "=r"(a) : "l"(p));
    return a;
}
__device__ __forceinline__ uint32_t f2tf32(float f) {
    uint32_t u;
    asm("cvt.rna.tf32.f32 %0, %1;" : "=r"(u) : "f"(f));
    return u;
}
__device__ __forceinline__ float f2tf32f(float f) {
    return __uint_as_float(f2tf32(f));
}
__device__ __forceinline__ void ldsm_x4(uint32_t* r, uint32_t a) {
    asm volatile("ldmatrix.sync.aligned.m8n8.x4.shared.b16 {%0,%1,%2,%3}, [%4];"
                 : "=r"(r[0]), "=r"(r[1]), "=r"(r[2]), "=r"(r[3]) : "r"(a));
}
__device__ __forceinline__ void mma_tf32(float* c, const uint32_t* a,
                                         uint32_t b0, uint32_t b1) {
    asm volatile(
        "mma.sync.aligned.m16n8k8.row.col.f32.tf32.tf32.f32 "
        "{%0,%1,%2,%3}, {%4,%5,%6,%7}, {%8,%9}, {%0,%1,%2,%3};"
        : "+f"(c[0]), "+f"(c[1]), "+f"(c[2]), "+f"(c[3])
        : "r"(a[0]), "r"(a[1]), "r"(a[2]), "r"(a[3]), "r"(b0), "r"(b1));
}

template <bool SHIFT>
__device__ __forceinline__ size_t tok_img_off(int T) {
    const int win = T >> 6, pos = T & 63;
    const int b = win >> 6, w = win & 63;
    int gr = (w >> 3) * 8 + (pos >> 3);
    int gc = (w & 7) * 8 + (pos & 7);
    if (SHIFT) { gr = (gr + 4) & 63; gc = (gc + 4) & 63; }
    return ((size_t)((b * 64 + gr) * 64 + gc)) * 256;
}
__device__ __forceinline__ int regid_of(int w, int pos) {
    const int gr = (w >> 3) * 8 + (pos >> 3);
    const int gc = (w & 7) * 8 + (pos & 7);
    const int rr = (gr < 56) ? 0 : (gr < 60 ? 1 : 2);
    const int cc = (gc < 56) ? 0 : (gc < 60 ? 1 : 2);
    return rr * 3 + cc;
}

// ---------------------------------------------------------------------------
// weight pre-pack (validated)
// ---------------------------------------------------------------------------
__global__ void prepack_w(const float* __restrict__ w, uint32_t* __restrict__ dst,
                          int NT)
{
    const int LDB = NT * 128;
    const int total = NT * 8 * 128 * 32;
    for (int idx = blockIdx.x * blockDim.x + threadIdx.x; idx < total;
         idx += gridDim.x * blockDim.x) {
        const int k   = idx & 31;
        const int n   = (idx >> 5) & 127;
        const int blk = idx >> 12;
        const int kc  = blk & 7, nt = blk >> 3;
        const float v = w[(size_t)(kc * 32 + k) * LDB + nt * 128 + n];
        dst[(size_t)(blk * 128 + n) * AST + k] = f2tf32(v);
    }
}

// ---------------------------------------------------------------------------
// tf32 mma.sync GEMM, 256 threads, 32x64 warp tiles  (R8-validated, EXACT)
// ---------------------------------------------------------------------------
template <int NT, bool LINEAR_A, bool LINEAR_OUT, bool SHIFT>
__global__ __launch_bounds__(256, 1)
void gemm_mma(const float* __restrict__ A, const uint32_t* __restrict__ Bp,
              const float* __restrict__ bias, float* __restrict__ Out)
{
    constexpr int LDB = NT * 128;
    extern __shared__ char smraw[];
    uint32_t* As = (uint32_t*)smraw;
    uint32_t* Bs = (uint32_t*)(smraw + 8 * CHUNK_B);
    const uint32_t smb = smem_u32(smraw);

    const int tid  = threadIdx.x;
    const int lane = tid & 31;
    const int wid  = tid >> 5;
    const int wm   = wid & 3;
    const int wn   = wid >> 2;
    const int mt   = blockIdx.x;

    {
        const int row = tid >> 1;
        const int T   = mt * 128 + row;
        const float* arow = LINEAR_A ? (A + (size_t)T * 256)
                                     : (A + tok_img_off<SHIFT>(T));
#pragma unroll
        for (int j = 0; j < 32; j++) {
            const int c4  = (tid & 1) * 32 + j;
            const float4 v = *((const float4*)arow + c4);
            const int col = c4 * 4;
            const int kc  = col >> 5, k = col & 31;
            uint4 u = { f2tf32(v.x), f2tf32(v.y), f2tf32(v.z), f2tf32(v.w) };
            *(uint4*)(As + (size_t)kc * (128 * AST) + row * AST + k) = u;
        }
    }

    const int a_row = (lane & 7) + ((lane >> 3) & 1) * 8;
    const int a_k   = ((lane >> 4) & 1) * 4;
    const int b_n   = (lane & 7);
    const int b_k   = (lane >> 3) * 4;

    float acc[2][8][4];
    const int total_cc = NT * 8;

    {
#pragma unroll
        for (int j = 0; j < 5; j++) {
            const int i = tid + j * 256;
            if (i < 1152) ((uint4*)Bs)[i] = ((const uint4*)Bp)[i];
        }
    }
    __syncthreads();

    for (int cc = 0; cc < total_cc; cc++) {
        const int nt  = cc >> 3;
        const int kc  = cc & 7;
        const int buf = cc & 1;

        if (kc == 0) {
#pragma unroll
            for (int mi = 0; mi < 2; mi++)
#pragma unroll
                for (int ni = 0; ni < 8; ni++)
#pragma unroll
                    for (int e = 0; e < 4; e++) acc[mi][ni][e] = 0.f;
        }

        uint4 pf[5];
        const bool more = (cc + 1 < total_cc);
        if (more) {
            const uint4* src = (const uint4*)(Bp + (size_t)(cc + 1) * (128 * AST));
#pragma unroll
            for (int j = 0; j < 5; j++) {
                const int i = tid + j * 256;
                if (i < 1152) pf[j] = src[i];
            }
        }

        const uint32_t a_base = smb + kc * CHUNK_B + ((wm * 32 + a_row) * AST) * 4;
        const uint32_t b_base = smb + 8 * CHUNK_B + buf * CHUNK_B
                              + ((wn * 64 + b_n) * AST) * 4;
#pragma unroll
        for (int kp = 0; kp < 2; kp++) {
            uint32_t bf[8][4];
#pragma unroll
            for (int ni = 0; ni < 8; ni++)
                ldsm_x4(bf[ni], b_base + (ni * 8) * AST * 4 + (kp * 16 + b_k) * 4);
#pragma unroll
            for (int half = 0; half < 2; half++) {
                const int ks = kp * 2 + half;
                uint32_t af[2][4];
#pragma unroll
                for (int mi = 0; mi < 2; mi++)
                    ldsm_x4(af[mi], a_base + (mi * 16) * AST * 4 + (ks * 8 + a_k) * 4);
#pragma unroll
                for (int mi = 0; mi < 2; mi++)
#pragma unroll
                    for (int ni = 0; ni < 8; ni++)
                        mma_tf32(acc[mi][ni], af[mi],
                                 bf[ni][half * 2], bf[ni][half * 2 + 1]);
            }
        }
        __syncthreads();
        if (more) {
            uint32_t* dstb = Bs + (size_t)((cc + 1) & 1) * (128 * AST);
#pragma unroll
            for (int j = 0; j < 5; j++) {
                const int i = tid + j * 256;
                if (i < 1152) ((uint4*)dstb)[i] = pf[j];
            }
            __syncthreads();
        }

        if (kc == 7) {
            const int g  = lane >> 2, tg = lane & 3;
            const int nb = nt * 128 + wn * 64;
#pragma unroll
            for (int mi = 0; mi < 2; mi++) {
#pragma unroll
                for (int hr = 0; hr < 2; hr++) {
                    const int T = mt * 128 + wm * 32 + mi * 16 + g + hr * 8;
                    float* orow = LINEAR_OUT ? (Out + (size_t)T * LDB)
                                             : (Out + tok_img_off<SHIFT>(T));
#pragma unroll
                    for (int ni = 0; ni < 8; ni++) {
                        const int c = nb + ni * 8 + 2 * tg;
                        float2 v;
                        v.x = acc[mi][ni][hr * 2]     + bias[c];
                        v.y = acc[mi][ni][hr * 2 + 1] + bias[c + 1];
                        *(float2*)(orow + c) = v;
                    }
                }
            }
        }
    }
}

// ---------------------------------------------------------------------------
// FUSED attention + output projection. CTA = window, 8 warps.
// Phase 1 (warp = head): S = QK^T, softmax, O = P@V kept in registers.
// Phase 2: ao chunks staged in dead K region; Wo streamed into dead V region;
//          proj GEMM (2m x 4n warps over 64x128 tiles) -> image scatter.
// ---------------------------------------------------------------------------
template <bool MASKED, bool SHIFT>
__global__ __launch_bounds__(256, 1)
void attn_proj(const float* __restrict__ qkv, const uint32_t* __restrict__ Bp,
               const float* __restrict__ bo, float* __restrict__ Out)
{
    extern __shared__ char smraw[];
    float* smf = (float*)smraw;
    const int tid  = threadIdx.x;
    const int lane = tid & 31;
    const int h    = tid >> 5;         // warp = head (phase 1)
    const int win  = blockIdx.x;
    const int w    = win & 63;
    const size_t Tb = (size_t)win * 64;

    float* qs = smf + QS_OFF + h * (16 * 36);
    float* ks = smf + KS_OFF + h * AO_CH;
    float* vt = smf + VT_OFF + h * (32 * 68);
    float* pb = smf + PB_OFF + h * (16 * 68);

    const float* hb = qkv + Tb * 768 + h * 32;

    // ---- stage K [64][32] and V^T [32][64] (tf32) ----
#pragma unroll
    for (int it = 0; it < 16; it++) {
        const int tok = it * 4 + (lane >> 3);
        const int d4  = lane & 7;
        const float4 kv = *(const float4*)(hb + (size_t)tok * 768 + 256 + d4 * 4);
        uint4 u = { f2tf32(kv.x), f2tf32(kv.y), f2tf32(kv.z), f2tf32(kv.w) };
        *(uint4*)(ks + tok * 36 + d4 * 4) = u;
        const float4 vv = *(const float4*)(hb + (size_t)tok * 768 + 512 + d4 * 4);
        const int db = d4 * 4;
        vt[(db + 0) * 68 + tok] = f2tf32f(vv.x);
        vt[(db + 1) * 68 + tok] = f2tf32f(vv.y);
        vt[(db + 2) * 68 + tok] = f2tf32f(vv.z);
        vt[(db + 3) * 68 + tok] = f2tf32f(vv.w);
    }

    const int g  = lane >> 2, tg = lane & 3;
    const int a_row = (lane & 7) + ((lane >> 3) & 1) * 8;
    const int a_k   = ((lane >> 4) & 1) * 4;
    const int b_n   = lane & 7;
    const int b_k   = (lane >> 3) * 4;

    const uint32_t qs_lm = smem_u32(qs) + (a_row * 36) * 4;
    const uint32_t pb_lm = smem_u32(pb) + (a_row * 68) * 4;
    const uint32_t ks_lm = smem_u32(ks) + (b_n * 36) * 4;
    const uint32_t vt_lm = smem_u32(vt) + (b_n * 68) * 4;

    int rid_c[16];
    if (MASKED) {
#pragma unroll
        for (int ni = 0; ni < 8; ni++) {
            rid_c[ni * 2]     = regid_of(w, ni * 8 + 2 * tg);
            rid_c[ni * 2 + 1] = regid_of(w, ni * 8 + 2 * tg + 1);
        }
    }
    __syncwarp();

    float o_all[4][4][4];           // O for all 4 query blocks, in registers

    for (int mi = 0; mi < 4; mi++) {
        // ---- Q block [16][32] ----
#pragma unroll
        for (int it = 0; it < 4; it++) {
            const int row = it * 4 + (lane >> 3);
            const int d4  = lane & 7;
            const float4 qv =
                *(const float4*)(hb + (size_t)(mi * 16 + row) * 768 + d4 * 4);
            uint4 u = { f2tf32(qv.x), f2tf32(qv.y), f2tf32(qv.z), f2tf32(qv.w) };
            *(uint4*)(qs + row * 36 + d4 * 4) = u;
        }
        __syncwarp();

        // ---- S = Q K^T ----
        float s[8][4];
#pragma unroll
        for (int ni = 0; ni < 8; ni++)
#pragma unroll
            for (int e = 0; e < 4; e++) s[ni][e] = 0.f;
#pragma unroll
        for (int kp = 0; kp < 2; kp++) {
            uint32_t bf[8][4];
#pragma unroll
            for (int ni = 0; ni < 8; ni++)
                ldsm_x4(bf[ni], ks_lm + (ni * 8) * 36 * 4 + (kp * 16 + b_k) * 4);
#pragma unroll
            for (int half = 0; half < 2; half++) {
                const int ksx = kp * 2 + half;
                uint32_t af[4];
                ldsm_x4(af, qs_lm + (ksx * 8 + a_k) * 4);
#pragma unroll
                for (int ni = 0; ni < 8; ni++)
                    mma_tf32(s[ni], af, bf[ni][half * 2], bf[ni][half * 2 + 1]);
            }
        }

        // ---- scale + mask ----
        int r0 = 0, r1 = 0;
        if (MASKED) {
            r0 = regid_of(w, mi * 16 + g);
            r1 = regid_of(w, mi * 16 + g + 8);
        }
#pragma unroll
        for (int ni = 0; ni < 8; ni++) {
#pragma unroll
            for (int e = 0; e < 2; e++) {
                s[ni][e]     = s[ni][e] * SCALE
                             + ((MASKED && r0 != rid_c[ni * 2 + e]) ? NEGM : 0.f);
                s[ni][2 + e] = s[ni][2 + e] * SCALE
                             + ((MASKED && r1 != rid_c[ni * 2 + e]) ? NEGM : 0.f);
            }
        }

        // ---- softmax ----
        float m0 = -3.0e38f, m1 = -3.0e38f;
#pragma unroll
        for (int ni = 0; ni < 8; ni++) {
            m0 = fmaxf(m0, fmaxf(s[ni][0], s[ni][1]));
            m1 = fmaxf(m1, fmaxf(s[ni][2], s[ni][3]));
        }
        m0 = fmaxf(m0, __shfl_xor_sync(0xffffffffu, m0, 1));
        m0 = fmaxf(m0, __shfl_xor_sync(0xffffffffu, m0, 2));
        m1 = fmaxf(m1, __shfl_xor_sync(0xffffffffu, m1, 1));
        m1 = fmaxf(m1, __shfl_xor_sync(0xffffffffu, m1, 2));
        float sum0 = 0.f, sum1 = 0.f;
#pragma unroll
        for (int ni = 0; ni < 8; ni++) {
            s[ni][0] = __expf(s[ni][0] - m0); sum0 += s[ni][0];
            s[ni][1] = __expf(s[ni][1] - m0); sum0 += s[ni][1];
            s[ni][2] = __expf(s[ni][2] - m1); sum1 += s[ni][2];
            s[ni][3] = __expf(s[ni][3] - m1); sum1 += s[ni][3];
        }
        sum0 += __shfl_xor_sync(0xffffffffu, sum0, 1);
        sum0 += __shfl_xor_sync(0xffffffffu, sum0, 2);
        sum1 += __shfl_xor_sync(0xffffffffu, sum1, 1);
        sum1 += __shfl_xor_sync(0xffffffffu, sum1, 2);
        const float i0 = 1.0f / sum0, i1 = 1.0f / sum1;

        // ---- P (tf32) -> pb ----
#pragma unroll
        for (int ni = 0; ni < 8; ni++) {
            float2 p0 = { f2tf32f(s[ni][0] * i0), f2tf32f(s[ni][1] * i0) };
            float2 p1 = { f2tf32f(s[ni][2] * i1), f2tf32f(s[ni][3] * i1) };
            *(float2*)(pb + g * 68 + ni * 8 + 2 * tg)       = p0;
            *(float2*)(pb + (g + 8) * 68 + ni * 8 + 2 * tg) = p1;
        }
        __syncwarp();

        // ---- O = P @ V, into o_all[mi] ----
        float (&o)[4][4] = o_all[mi];
#pragma unroll
        for (int ni = 0; ni < 4; ni++)
#pragma unroll
            for (int e = 0; e < 4; e++) o[ni][e] = 0.f;
#pragma unroll
        for (int kp = 0; kp < 4; kp++) {
            uint32_t bf2[4][4];
#pragma unroll
            for (int ni = 0; ni < 4; ni++)
                ldsm_x4(bf2[ni], vt_lm + (ni * 8) * 68 * 4 + (kp * 16 + b_k) * 4);
#pragma unroll
            for (int half = 0; half < 2; half++) {
                const int ksx = kp * 2 + half;
                uint32_t af[4];
                ldsm_x4(af, pb_lm + (ksx * 8 + a_k) * 4);
#pragma unroll
                for (int ni = 0; ni < 4; ni++)
                    mma_tf32(o[ni], af, bf2[ni][half * 2], bf2[ni][half * 2 + 1]);
            }
        }
        __syncwarp();   // pb reads done before next mi overwrites
    }

    // ---- stage ao (tf32) into dead K region: chunk h = head h's 32 cols ----
    // ks[row][k], row = token 0..63, k = col within head
#pragma unroll
    for (int mi = 0; mi < 4; mi++) {
#pragma unroll
        for (int ni = 0; ni < 4; ni++) {
            const int c = ni * 8 + 2 * tg;
            *(float2*)(ks + (mi * 16 + g) * 36 + c) =
                make_float2(f2tf32f(o_all[mi][ni][0]), f2tf32f(o_all[mi][ni][1]));
            *(float2*)(ks + (mi * 16 + g + 8) * 36 + c) =
                make_float2(f2tf32f(o_all[mi][ni][2]), f2tf32f(o_all[mi][ni][3]));
        }
    }
    __syncthreads();   // all attention done: V region reusable as Wo ring

    // ================= phase 2: out = ao @ Wo + bo =================
    const uint32_t smb = smem_u32(smf);
    const uint32_t ao_base = smb + KS_OFF * 4;
    uint32_t* Bs = (uint32_t*)(smf + VT_OFF);        // ring: 2 x [128][36]

    const int wm = (tid >> 5) & 1;       // 32-row band (2 bands over 64 rows)
    const int wn = (tid >> 5) >> 1;      // 32-col band within 128-col n-tile

    // prologue: STS Wo chunk 0
    {
#pragma unroll
        for (int j = 0; j < 5; j++) {
            const int i = tid + j * 256;
            if (i < 1152) ((uint4*)Bs)[i] = ((const uint4*)Bp)[i];
        }
    }
    __syncthreads();

    float acc[2][4][4];
    for (int cc = 0; cc < 16; cc++) {
        const int nt  = cc >> 3;
        const int kc  = cc & 7;
        const int buf = cc & 1;

        if (kc == 0) {
#pragma unroll
            for (int mi = 0; mi < 2; mi++)
#pragma unroll
                for (int ni = 0; ni < 4; ni++)
#pragma unroll
                    for (int e = 0; e < 4; e++) acc[mi][ni][e] = 0.f;
        }

        uint4 pf[5];
        const bool more = (cc + 1 < 16);
        if (more) {
            const uint4* src = (const uint4*)(Bp + (size_t)(cc + 1) * (128 * AST));
#pragma unroll
            for (int j = 0; j < 5; j++) {
                const int i = tid + j * 256;
                if (i < 1152) pf[j] = src[i];
            }
        }

        const uint32_t a_base = ao_base + kc * (AO_CH * 4)
                              + ((wm * 32 + a_row) * 36) * 4;
        const uint32_t b_base = smem_u32(Bs) + buf * CHUNK_B
                              + ((wn * 32 + b_n) * 36) * 4;
#pragma unroll
        for (int kp = 0; kp < 2; kp++) {
            uint32_t bf[4][4];
#pragma unroll
            for (int ni = 0; ni < 4; ni++)
                ldsm_x4(bf[ni], b_base + (ni * 8) * 36 * 4 + (kp * 16 + b_k) * 4);
#pragma unroll
            for (int half = 0; half < 2; half++) {
                const int ksx = kp * 2 + half;
                uint32_t af[2][4];
#pragma unroll
                for (int mi = 0; mi < 2; mi++)
                    ldsm_x4(af[mi], a_base + (mi * 16) * 36 * 4 + (ksx * 8 + a_k) * 4);
#pragma unroll
                for (int mi = 0; mi < 2; mi++)
#pragma unroll
                    for (int ni = 0; ni < 4; ni++)
                        mma_tf32(acc[mi][ni], af[mi],
                                 bf[ni][half * 2], bf[ni][half * 2 + 1]);
            }
        }
        __syncthreads();
        if (more) {
            uint32_t* dstb = Bs + (size_t)((cc + 1) & 1) * (128 * AST);
#pragma unroll
            for (int j = 0; j < 5; j++) {
                const int i = tid + j * 256;
                if (i < 1152) ((uint4*)dstb)[i] = pf[j];
            }
            __syncthreads();
        }

        if (kc == 7) {
            const int nb = nt * 128 + wn * 32;
#pragma unroll
            for (int mi = 0; mi < 2; mi++) {
#pragma unroll
                for (int hr = 0; hr < 2; hr++) {
                    const int row = wm * 32 + mi * 16 + g + hr * 8;     // token 0..63
                    float* orow = Out + tok_img_off<SHIFT>((int)(Tb + row));
#pragma unroll
                    for (int ni = 0; ni < 4; ni++) {
                        const int c = nb + ni * 8 + 2 * tg;
                        float2 v;
                        v.x = acc[mi][ni][hr * 2]     + bo[c];
                        v.y = acc[mi][ni][hr * 2 + 1] + bo[c + 1];
                        *(float2*)(orow + c) = v;
                    }
                }
            }
        }
    }
}

// ---------------------------------------------------------------------------
extern "C" void kernel_launch(void* const* d_in, const int* in_sizes, int n_in,
                              void* d_out, int out_size)
{
    const float* x    = (const float*)d_in[0];
    const float* wqkv = (const float*)d_in[1];
    const float* bqkv = (const float*)d_in[2];
    const float* wo   = (const float*)d_in[3];
    const float* bo   = (const float*)d_in[4];
    float* out = (float*)d_out;

    float *qkv_p, *y_p;
    uint32_t *wq_p, *wo_pk;
    cudaGetSymbolAddress((void**)&qkv_p, g_qkv);
    cudaGetSymbolAddress((void**)&y_p,   g_y);
    cudaGetSymbolAddress((void**)&wq_p,  g_wqkv_p);
    cudaGetSymbolAddress((void**)&wo_pk, g_wo_p);

    cudaFuncSetAttribute(gemm_mma<6, false, true,  false>,
                         cudaFuncAttributeMaxDynamicSharedMemorySize, GSMEM);
    cudaFuncSetAttribute(gemm_mma<6, false, true,  true>,
                         cudaFuncAttributeMaxDynamicSharedMemorySize, GSMEM);
    cudaFuncSetAttribute(attn_proj<false, false>,
                         cudaFuncAttributeMaxDynamicSharedMemorySize, ASMEM);
    cudaFuncSetAttribute(attn_proj<true, true>,
                         cudaFuncAttributeMaxDynamicSharedMemorySize, ASMEM);

    prepack_w<<<192, 256>>>(wqkv, wq_p, 6);
    prepack_w<<<64,  256>>>(wo,   wo_pk, 2);

    // pass 1 (unshifted): qkv GEMM -> fused attn+proj -> g_y (image layout)
    gemm_mma<6, false, true,  false><<<MT, 256, GSMEM>>>(x,   wq_p, bqkv, qkv_p);
    attn_proj<false, false><<<2048, 256, ASMEM>>>(qkv_p, wo_pk, bo, y_p);
    // pass 2 (shifted + mask): qkv GEMM (gather+roll) -> fused -> out (inv roll)
    gemm_mma<6, false, true,  true ><<<MT, 256, GSMEM>>>(y_p, wq_p, bqkv, qkv_p);
    attn_proj<true, true><<<2048, 256, ASMEM>>>(qkv_p, wo_pk, bo, out);
}

// round 13
// speedup vs baseline: 2.0461x; 1.2864x over previous
#include <cuda_runtime.h>
#include <cuda_fp16.h>
#include <cstdint>

// ===========================================================================
// SWIN attention layer on GB300 (sm_103 base target — NO tcgen05).
// R12: ALL matmuls via mma.sync.m16n8k16.f16 (fp32 accum) + ldmatrix.b16.
// fp16 mantissa == tf32 mantissa (10 bits) -> same rounding error, 2x rate.
// Pipeline per pass: QKV GEMM -> fused attention+output-proj kernel.
// ===========================================================================

namespace {
constexpr int TOK = 32 * 64 * 64;          // 131072 tokens
constexpr int MT  = TOK / 128;             // 1024 M-tiles
constexpr float SCALE = 0.17677669529663687f;
constexpr float NEGM  = -1e9f;
constexpr int HST = 40;                    // smem row stride (halfs) for 32-half rows
constexpr int CHUNK_H = 128 * HST;         // 5120 halfs = 10240 B per [128][32] tile
constexpr int GSMEM = (8 * CHUNK_H + 2 * CHUNK_H) * 2;   // 102400 B

// fused attn+proj smem layout (halfs)
constexpr int QS_OFF = 0;                          // [8][16][40]  Q staging
constexpr int KS_OFF = QS_OFF + 8 * 16 * 40;       // [8][64][40]  K, then ao chunks
constexpr int VT_OFF = KS_OFF + 8 * 64 * 40;       // [8][32][72]  V^T, then Wo ring
constexpr int PB_OFF = VT_OFF + 8 * 32 * 72;       // [8][16][72]  P staging
constexpr int ASMEM  = (PB_OFF + 8 * 16 * 72) * 2; // 106496 B
constexpr int AO_CH  = 64 * HST;                   // halfs per ao chunk
}

// static device scratch
__device__ float  g_qkv[(size_t)TOK * 768];
__device__ float  g_y  [(size_t)TOK * 256];
__device__ __half g_wqkv_h[6 * 8 * 128 * HST];
__device__ __half g_wo_h  [2 * 8 * 128 * HST];

__device__ __forceinline__ uint32_t smem_u32(const void* p) {
    uint32_t a;
    asm("{ .reg .u64 t; cvta.to.shared.u64 t, %1; cvt.u32.u64 %0, t; }"
        : "=r"(a) : "l"(p));
    return a;
}
__device__ __forceinline__ uint32_t pack_h2(float a, float b) {
    __half2 h = __floats2half2_rn(a, b);
    return *(uint32_t*)&h;
}
__device__ __forceinline__ void ldsm_x4(uint32_t* r, uint32_t a) {
    asm volatile("ldmatrix.sync.aligned.m8n8.x4.shared.b16 {%0,%1,%2,%3}, [%4];"
                 : "=r"(r[0]), "=r"(r[1]), "=r"(r[2]), "=r"(r[3]) : "r"(a));
}
__device__ __forceinline__ void mma_f16(float* c, const uint32_t* a,
                                        uint32_t b0, uint32_t b1) {
    asm volatile(
        "mma.sync.aligned.m16n8k16.row.col.f32.f16.f16.f32 "
        "{%0,%1,%2,%3}, {%4,%5,%6,%7}, {%8,%9}, {%0,%1,%2,%3};"
        : "+f"(c[0]), "+f"(c[1]), "+f"(c[2]), "+f"(c[3])
        : "r"(a[0]), "r"(a[1]), "r"(a[2]), "r"(a[3]), "r"(b0), "r"(b1));
}

template <bool SHIFT>
__device__ __forceinline__ size_t tok_img_off(int T) {
    const int win = T >> 6, pos = T & 63;
    const int b = win >> 6, w = win & 63;
    int gr = (w >> 3) * 8 + (pos >> 3);
    int gc = (w & 7) * 8 + (pos & 7);
    if (SHIFT) { gr = (gr + 4) & 63; gc = (gc + 4) & 63; }
    return ((size_t)((b * 64 + gr) * 64 + gc)) * 256;
}
__device__ __forceinline__ int regid_of(int w, int pos) {
    const int gr = (w >> 3) * 8 + (pos >> 3);
    const int gc = (w & 7) * 8 + (pos & 7);
    const int rr = (gr < 56) ? 0 : (gr < 60 ? 1 : 2);
    const int cc = (gc < 56) ? 0 : (gc < 60 ? 1 : 2);
    return rr * 3 + cc;
}

// ---------------------------------------------------------------------------
// weight pre-pack: W[K=256][N] fp32 -> per (nt,kc) [n 128][k 32] halfs, stride 40
// ---------------------------------------------------------------------------
__global__ void prepack_w(const float* __restrict__ w, __half* __restrict__ dst,
                          int NT)
{
    const int LDB = NT * 128;
    const int total = NT * 8 * 128 * 32;
    for (int idx = blockIdx.x * blockDim.x + threadIdx.x; idx < total;
         idx += gridDim.x * blockDim.x) {
        const int k   = idx & 31;
        const int n   = (idx >> 5) & 127;
        const int blk = idx >> 12;
        const int kc  = blk & 7, nt = blk >> 3;
        const float v = w[(size_t)(kc * 32 + k) * LDB + nt * 128 + n];
        dst[(size_t)(blk * 128 + n) * HST + k] = __float2half(v);
    }
}

// ---------------------------------------------------------------------------
// fp16 mma GEMM: C[128 x NT*128] = A[128x256] @ W + bias. 256 thr, 32x64 tiles.
// ---------------------------------------------------------------------------
template <int NT, bool LINEAR_A, bool SHIFT>
__global__ __launch_bounds__(256, 2)
void gemm_mma(const float* __restrict__ A, const __half* __restrict__ Bp,
              const float* __restrict__ bias, float* __restrict__ Out)
{
    constexpr int LDB = NT * 128;
    extern __shared__ char smraw[];
    __half* As = (__half*)smraw;
    __half* Bs = (__half*)(smraw + 8 * CHUNK_H * 2);
    const uint32_t smb = smem_u32(smraw);

    const int tid  = threadIdx.x;
    const int lane = tid & 31;
    const int wid  = tid >> 5;
    const int wm   = wid & 3;
    const int wn   = wid >> 2;
    const int mt   = blockIdx.x;

    // ---- A gather + fp16 convert into 8 K-chunk smem tiles ----
    {
        const int row = tid >> 1;
        const int T   = mt * 128 + row;
        const float* arow = LINEAR_A ? (A + (size_t)T * 256)
                                     : (A + tok_img_off<SHIFT>(T));
#pragma unroll
        for (int j = 0; j < 32; j++) {
            const int c4  = (tid & 1) * 32 + j;
            const float4 v = *((const float4*)arow + c4);
            const int col = c4 * 4;
            const int kc  = col >> 5, k = col & 31;
            uint2 u = { pack_h2(v.x, v.y), pack_h2(v.z, v.w) };
            *(uint2*)(As + (size_t)kc * CHUNK_H + row * HST + k) = u;
        }
    }

    const int a_row = (lane & 7) + ((lane >> 3) & 1) * 8;
    const int a_kb  = (lane >> 4) * 16;            // byte offset within k16
    const int b_n   = (lane & 7);
    const int b_kb  = (lane >> 3) * 16;            // k-half index * 16B

    float acc[2][8][4];
    const int total_cc = NT * 8;

    // prologue: STS B chunk 0 (640 uint4 per chunk)
    {
#pragma unroll
        for (int j = 0; j < 3; j++) {
            const int i = tid + j * 256;
            if (i < 640) ((uint4*)Bs)[i] = ((const uint4*)Bp)[i];
        }
    }
    __syncthreads();

    for (int cc = 0; cc < total_cc; cc++) {
        const int nt  = cc >> 3;
        const int kc  = cc & 7;
        const int buf = cc & 1;

        if (kc == 0) {
#pragma unroll
            for (int mi = 0; mi < 2; mi++)
#pragma unroll
                for (int ni = 0; ni < 8; ni++)
#pragma unroll
                    for (int e = 0; e < 4; e++) acc[mi][ni][e] = 0.f;
        }

        uint4 pf[3];
        const bool more = (cc + 1 < total_cc);
        if (more) {
            const uint4* src = (const uint4*)(Bp + (size_t)(cc + 1) * CHUNK_H);
#pragma unroll
            for (int j = 0; j < 3; j++) {
                const int i = tid + j * 256;
                if (i < 640) pf[j] = src[i];
            }
        }

        const uint32_t a_base = smb + (kc * CHUNK_H + (wm * 32 + a_row) * HST) * 2 + a_kb;
        const uint32_t b_base = smb + (8 * CHUNK_H + buf * CHUNK_H
                              + (wn * 64 + b_n) * HST) * 2 + b_kb;

        uint32_t bf[8][4];
#pragma unroll
        for (int ni = 0; ni < 8; ni++)
            ldsm_x4(bf[ni], b_base + (ni * 8) * (HST * 2));   // covers k 0..31
#pragma unroll
        for (int ks = 0; ks < 2; ks++) {
            uint32_t af[2][4];
#pragma unroll
            for (int mi = 0; mi < 2; mi++)
                ldsm_x4(af[mi], a_base + (mi * 16) * (HST * 2) + ks * 32);
#pragma unroll
            for (int mi = 0; mi < 2; mi++)
#pragma unroll
                for (int ni = 0; ni < 8; ni++)
                    mma_f16(acc[mi][ni], af[mi], bf[ni][2 * ks], bf[ni][2 * ks + 1]);
        }
        __syncthreads();
        if (more) {
            __half* dstb = Bs + (size_t)((cc + 1) & 1) * CHUNK_H;
#pragma unroll
            for (int j = 0; j < 3; j++) {
                const int i = tid + j * 256;
                if (i < 640) ((uint4*)dstb)[i] = pf[j];
            }
            __syncthreads();
        }

        if (kc == 7) {
            const int g  = lane >> 2, tg = lane & 3;
            const int nb = nt * 128 + wn * 64;
#pragma unroll
            for (int mi = 0; mi < 2; mi++) {
#pragma unroll
                for (int hr = 0; hr < 2; hr++) {
                    const int T = mt * 128 + wm * 32 + mi * 16 + g + hr * 8;
                    float* orow = Out + (size_t)T * LDB;
#pragma unroll
                    for (int ni = 0; ni < 8; ni++) {
                        const int c = nb + ni * 8 + 2 * tg;
                        float2 v;
                        v.x = acc[mi][ni][hr * 2]     + bias[c];
                        v.y = acc[mi][ni][hr * 2 + 1] + bias[c + 1];
                        *(float2*)(orow + c) = v;
                    }
                }
            }
        }
    }
}

// ---------------------------------------------------------------------------
// FUSED attention + output projection (fp16 mma). CTA = window, 8 warps.
// ---------------------------------------------------------------------------
template <bool MASKED, bool SHIFT>
__global__ __launch_bounds__(256, 1)
void attn_proj(const float* __restrict__ qkv, const __half* __restrict__ Bp,
               const float* __restrict__ bo, float* __restrict__ Out)
{
    extern __shared__ char smraw[];
    __half* smh = (__half*)smraw;
    const int tid  = threadIdx.x;
    const int lane = tid & 31;
    const int h    = tid >> 5;
    const int win  = blockIdx.x;
    const int w    = win & 63;
    const size_t Tb = (size_t)win * 64;

    __half* qs = smh + QS_OFF + h * (16 * 40);
    __half* ks = smh + KS_OFF + h * AO_CH;
    __half* vt = smh + VT_OFF + h * (32 * 72);
    __half* pb = smh + PB_OFF + h * (16 * 72);

    const float* hb = qkv + Tb * 768 + h * 32;

    // ---- stage K [64][32] and V^T [32][64] as fp16 ----
#pragma unroll
    for (int it = 0; it < 16; it++) {
        const int tok = it * 4 + (lane >> 3);
        const int d4  = lane & 7;
        const float4 kv = *(const float4*)(hb + (size_t)tok * 768 + 256 + d4 * 4);
        uint2 u = { pack_h2(kv.x, kv.y), pack_h2(kv.z, kv.w) };
        *(uint2*)(ks + tok * 40 + d4 * 4) = u;
        const float4 vv = *(const float4*)(hb + (size_t)tok * 768 + 512 + d4 * 4);
        const int db = d4 * 4;
        vt[(db + 0) * 72 + tok] = __float2half(vv.x);
        vt[(db + 1) * 72 + tok] = __float2half(vv.y);
        vt[(db + 2) * 72 + tok] = __float2half(vv.z);
        vt[(db + 3) * 72 + tok] = __float2half(vv.w);
    }

    const int g  = lane >> 2, tg = lane & 3;
    const int a_row = (lane & 7) + ((lane >> 3) & 1) * 8;
    const int a_kb  = (lane >> 4) * 16;
    const int b_n   = lane & 7;
    const int b_kb  = (lane >> 3) * 16;

    const uint32_t qs_lm = smem_u32(qs) + a_row * 80 + a_kb;
    const uint32_t pb_lm = smem_u32(pb) + a_row * 144 + a_kb;
    const uint32_t ks_lm = smem_u32(ks) + b_n * 80 + b_kb;
    const uint32_t vt_lm = smem_u32(vt) + b_n * 144 + b_kb;

    int rid_c[16];
    if (MASKED) {
#pragma unroll
        for (int ni = 0; ni < 8; ni++) {
            rid_c[ni * 2]     = regid_of(w, ni * 8 + 2 * tg);
            rid_c[ni * 2 + 1] = regid_of(w, ni * 8 + 2 * tg + 1);
        }
    }
    __syncwarp();

    float o_all[4][4][4];

    for (int mi = 0; mi < 4; mi++) {
        // ---- Q block [16][32] ----
#pragma unroll
        for (int it = 0; it < 4; it++) {
            const int row = it * 4 + (lane >> 3);
            const int d4  = lane & 7;
            const float4 qv =
                *(const float4*)(hb + (size_t)(mi * 16 + row) * 768 + d4 * 4);
            uint2 u = { pack_h2(qv.x, qv.y), pack_h2(qv.z, qv.w) };
            *(uint2*)(qs + row * 40 + d4 * 4) = u;
        }
        __syncwarp();

        // ---- S = Q K^T ----
        float s[8][4];
#pragma unroll
        for (int ni = 0; ni < 8; ni++)
#pragma unroll
            for (int e = 0; e < 4; e++) s[ni][e] = 0.f;
        {
            uint32_t bf[8][4];
#pragma unroll
            for (int ni = 0; ni < 8; ni++)
                ldsm_x4(bf[ni], ks_lm + (ni * 8) * 80);
#pragma unroll
            for (int ksx = 0; ksx < 2; ksx++) {
                uint32_t af[4];
                ldsm_x4(af, qs_lm + ksx * 32);
#pragma unroll
                for (int ni = 0; ni < 8; ni++)
                    mma_f16(s[ni], af, bf[ni][2 * ksx], bf[ni][2 * ksx + 1]);
            }
        }

        // ---- scale + mask ----
        int r0 = 0, r1 = 0;
        if (MASKED) {
            r0 = regid_of(w, mi * 16 + g);
            r1 = regid_of(w, mi * 16 + g + 8);
        }
#pragma unroll
        for (int ni = 0; ni < 8; ni++) {
#pragma unroll
            for (int e = 0; e < 2; e++) {
                s[ni][e]     = s[ni][e] * SCALE
                             + ((MASKED && r0 != rid_c[ni * 2 + e]) ? NEGM : 0.f);
                s[ni][2 + e] = s[ni][2 + e] * SCALE
                             + ((MASKED && r1 != rid_c[ni * 2 + e]) ? NEGM : 0.f);
            }
        }

        // ---- softmax ----
        float m0 = -3.0e38f, m1 = -3.0e38f;
#pragma unroll
        for (int ni = 0; ni < 8; ni++) {
            m0 = fmaxf(m0, fmaxf(s[ni][0], s[ni][1]));
            m1 = fmaxf(m1, fmaxf(s[ni][2], s[ni][3]));
        }
        m0 = fmaxf(m0, __shfl_xor_sync(0xffffffffu, m0, 1));
        m0 = fmaxf(m0, __shfl_xor_sync(0xffffffffu, m0, 2));
        m1 = fmaxf(m1, __shfl_xor_sync(0xffffffffu, m1, 1));
        m1 = fmaxf(m1, __shfl_xor_sync(0xffffffffu, m1, 2));
        float sum0 = 0.f, sum1 = 0.f;
#pragma unroll
        for (int ni = 0; ni < 8; ni++) {
            s[ni][0] = __expf(s[ni][0] - m0); sum0 += s[ni][0];
            s[ni][1] = __expf(s[ni][1] - m0); sum0 += s[ni][1];
            s[ni][2] = __expf(s[ni][2] - m1); sum1 += s[ni][2];
            s[ni][3] = __expf(s[ni][3] - m1); sum1 += s[ni][3];
        }
        sum0 += __shfl_xor_sync(0xffffffffu, sum0, 1);
        sum0 += __shfl_xor_sync(0xffffffffu, sum0, 2);
        sum1 += __shfl_xor_sync(0xffffffffu, sum1, 1);
        sum1 += __shfl_xor_sync(0xffffffffu, sum1, 2);
        const float i0 = 1.0f / sum0, i1 = 1.0f / sum1;

        // ---- P (fp16) -> pb ----
#pragma unroll
        for (int ni = 0; ni < 8; ni++) {
            *(uint32_t*)(pb + g * 72 + ni * 8 + 2 * tg) =
                pack_h2(s[ni][0] * i0, s[ni][1] * i0);
            *(uint32_t*)(pb + (g + 8) * 72 + ni * 8 + 2 * tg) =
                pack_h2(s[ni][2] * i1, s[ni][3] * i1);
        }
        __syncwarp();

        // ---- O = P @ V ----
        float (&o)[4][4] = o_all[mi];
#pragma unroll
        for (int ni = 0; ni < 4; ni++)
#pragma unroll
            for (int e = 0; e < 4; e++) o[ni][e] = 0.f;
#pragma unroll
        for (int kp = 0; kp < 2; kp++) {           // token halves 0-31 / 32-63
            uint32_t bf2[4][4];
#pragma unroll
            for (int ni = 0; ni < 4; ni++)
                ldsm_x4(bf2[ni], vt_lm + (ni * 8) * 144 + kp * 64);
#pragma unroll
            for (int ks2 = 0; ks2 < 2; ks2++) {
                uint32_t af[4];
                ldsm_x4(af, pb_lm + kp * 64 + ks2 * 32);
#pragma unroll
                for (int ni = 0; ni < 4; ni++)
                    mma_f16(o[ni], af, bf2[ni][2 * ks2], bf2[ni][2 * ks2 + 1]);
            }
        }
        __syncwarp();   // pb reads done before next mi overwrites
    }

    // ---- stage ao (fp16) into dead K region: chunk h = head h's 32 cols ----
#pragma unroll
    for (int mi = 0; mi < 4; mi++) {
#pragma unroll
        for (int ni = 0; ni < 4; ni++) {
            const int c = ni * 8 + 2 * tg;
            *(uint32_t*)(ks + (mi * 16 + g) * 40 + c) =
                pack_h2(o_all[mi][ni][0], o_all[mi][ni][1]);
            *(uint32_t*)(ks + (mi * 16 + g + 8) * 40 + c) =
                pack_h2(o_all[mi][ni][2], o_all[mi][ni][3]);
        }
    }
    __syncthreads();   // attention done: V/P regions dead, ao staged

    // ================= phase 2: out = ao @ Wo + bo =================
    const uint32_t smb = smem_u32(smh);
    const uint32_t ao_base = smb + KS_OFF * 2;
    __half* Bs = smh + VT_OFF;                   // ring: 2 x [128][40] halfs

    const int wm = (tid >> 5) & 1;
    const int wn = (tid >> 5) >> 1;

    {
#pragma unroll
        for (int j = 0; j < 3; j++) {
            const int i = tid + j * 256;
            if (i < 640) ((uint4*)Bs)[i] = ((const uint4*)Bp)[i];
        }
    }
    __syncthreads();

    float acc[2][4][4];
    for (int cc = 0; cc < 16; cc++) {
        const int nt  = cc >> 3;
        const int kc  = cc & 7;
        const int buf = cc & 1;

        if (kc == 0) {
#pragma unroll
            for (int mi = 0; mi < 2; mi++)
#pragma unroll
                for (int ni = 0; ni < 4; ni++)
#pragma unroll
                    for (int e = 0; e < 4; e++) acc[mi][ni][e] = 0.f;
        }

        uint4 pf[3];
        const bool more = (cc + 1 < 16);
        if (more) {
            const uint4* src = (const uint4*)(Bp + (size_t)(cc + 1) * CHUNK_H);
#pragma unroll
            for (int j = 0; j < 3; j++) {
                const int i = tid + j * 256;
                if (i < 640) pf[j] = src[i];
            }
        }

        const uint32_t a_base = ao_base + (kc * AO_CH + (wm * 32 + a_row) * 40) * 2 + a_kb;
        const uint32_t b_base = smem_u32(Bs) + (buf * CHUNK_H + (wn * 32 + b_n) * 40) * 2 + b_kb;

        uint32_t bf[4][4];
#pragma unroll
        for (int ni = 0; ni < 4; ni++)
            ldsm_x4(bf[ni], b_base + (ni * 8) * 80);
#pragma unroll
        for (int ksx = 0; ksx < 2; ksx++) {
            uint32_t af[2][4];
#pragma unroll
            for (int mi = 0; mi < 2; mi++)
                ldsm_x4(af[mi], a_base + (mi * 16) * 80 + ksx * 32);
#pragma unroll
            for (int mi = 0; mi < 2; mi++)
#pragma unroll
                for (int ni = 0; ni < 4; ni++)
                    mma_f16(acc[mi][ni], af[mi], bf[ni][2 * ksx], bf[ni][2 * ksx + 1]);
        }
        __syncthreads();
        if (more) {
            __half* dstb = Bs + (size_t)((cc + 1) & 1) * CHUNK_H;
#pragma unroll
            for (int j = 0; j < 3; j++) {
                const int i = tid + j * 256;
                if (i < 640) ((uint4*)dstb)[i] = pf[j];
            }
            __syncthreads();
        }

        if (kc == 7) {
            const int nb = nt * 128 + wn * 32;
#pragma unroll
            for (int mi = 0; mi < 2; mi++) {
#pragma unroll
                for (int hr = 0; hr < 2; hr++) {
                    const int row = wm * 32 + mi * 16 + g + hr * 8;
                    float* orow = Out + tok_img_off<SHIFT>((int)(Tb + row));
#pragma unroll
                    for (int ni = 0; ni < 4; ni++) {
                        const int c = nb + ni * 8 + 2 * tg;
                        float2 v;
                        v.x = acc[mi][ni][hr * 2]     + bo[c];
                        v.y = acc[mi][ni][hr * 2 + 1] + bo[c + 1];
                        *(float2*)(orow + c) = v;
                    }
                }
            }
        }
    }
}

// ---------------------------------------------------------------------------
extern "C" void kernel_launch(void* const* d_in, const int* in_sizes, int n_in,
                              void* d_out, int out_size)
{
    const float* x    = (const float*)d_in[0];
    const float* wqkv = (const float*)d_in[1];
    const float* bqkv = (const float*)d_in[2];
    const float* wo   = (const float*)d_in[3];
    const float* bo   = (const float*)d_in[4];
    float* out = (float*)d_out;

    float *qkv_p, *y_p;
    __half *wq_p, *wo_pk;
    cudaGetSymbolAddress((void**)&qkv_p, g_qkv);
    cudaGetSymbolAddress((void**)&y_p,   g_y);
    cudaGetSymbolAddress((void**)&wq_p,  g_wqkv_h);
    cudaGetSymbolAddress((void**)&wo_pk, g_wo_h);

    cudaFuncSetAttribute(gemm_mma<6, false, false>,
                         cudaFuncAttributeMaxDynamicSharedMemorySize, GSMEM);
    cudaFuncSetAttribute(gemm_mma<6, false, true>,
                         cudaFuncAttributeMaxDynamicSharedMemorySize, GSMEM);
    cudaFuncSetAttribute(attn_proj<false, false>,
                         cudaFuncAttributeMaxDynamicSharedMemorySize, ASMEM);
    cudaFuncSetAttribute(attn_proj<true, true>,
                         cudaFuncAttributeMaxDynamicSharedMemorySize, ASMEM);

    prepack_w<<<192, 256>>>(wqkv, wq_p, 6);
    prepack_w<<<64,  256>>>(wo,   wo_pk, 2);

    // pass 1 (unshifted): qkv GEMM -> fused attn+proj -> g_y (image layout)
    gemm_mma<6, false, false><<<MT, 256, GSMEM>>>(x,   wq_p, bqkv, qkv_p);
    attn_proj<false, false><<<2048, 256, ASMEM>>>(qkv_p, wo_pk, bo, y_p);
    // pass 2: qkv GEMM gathers from image-layout g_y with roll (LINEAR_A=false!)
    gemm_mma<6, false, true><<<MT, 256, GSMEM>>>(y_p, wq_p, bqkv, qkv_p);
    attn_proj<true, true><<<2048, 256, ASMEM>>>(qkv_p, wo_pk, bo, out);
}

// round 14
// speedup vs baseline: 2.2860x; 1.1172x over previous
#include <cuda_runtime.h>
#include <cuda_fp16.h>
#include <cstdint>

// ===========================================================================
// SWIN attention layer on GB300 (sm_103 base target — NO tcgen05).
// R14: fp16 mma.m16n8k16 everywhere + fp16 intermediates (g_qkv, g_y).
// Pipeline per pass: QKV GEMM -> fused attention+output-proj kernel.
// ===========================================================================

namespace {
constexpr int TOK = 32 * 64 * 64;          // 131072 tokens
constexpr int MT  = TOK / 128;             // 1024 M-tiles
constexpr float SCALE = 0.17677669529663687f;
constexpr float NEGM  = -1e9f;
constexpr int HST = 40;                    // smem row stride (halfs)
constexpr int CHUNK_H = 128 * HST;         // 5120 halfs per [128][32] tile
constexpr int GSMEM = (8 * CHUNK_H + 2 * CHUNK_H) * 2;   // 102400 B

// fused attn+proj smem layout (halfs)
constexpr int QS_OFF = 0;                          // [8][16][40]  Q staging
constexpr int KS_OFF = QS_OFF + 8 * 16 * 40;       // [8][64][40]  K, then ao
constexpr int VT_OFF = KS_OFF + 8 * 64 * 40;       // [8][32][72]  V^T, then Wo
constexpr int PB_OFF = VT_OFF + 8 * 32 * 72;       // [8][16][72]  P staging
constexpr int ASMEM  = (PB_OFF + 8 * 16 * 72) * 2; // 106496 B
constexpr int AO_CH  = 64 * HST;
}

// static device scratch (fp16 intermediates)
__device__ __half g_qkv[(size_t)TOK * 768];
__device__ __half g_y  [(size_t)TOK * 256];
__device__ __half g_wqkv_h[6 * 8 * 128 * HST];
__device__ __half g_wo_h  [2 * 8 * 128 * HST];

__device__ __forceinline__ uint32_t smem_u32(const void* p) {
    uint32_t a;
    asm("{ .reg .u64 t; cvta.to.shared.u64 t, %1; cvt.u32.u64 %0, t; }"
        : "=r"(a) : "l"(p));
    return a;
}
__device__ __forceinline__ uint32_t pack_h2(float a, float b) {
    __half2 h = __floats2half2_rn(a, b);
    return *(uint32_t*)&h;
}
__device__ __forceinline__ void ldsm_x4(uint32_t* r, uint32_t a) {
    asm volatile("ldmatrix.sync.aligned.m8n8.x4.shared.b16 {%0,%1,%2,%3}, [%4];"
                 : "=r"(r[0]), "=r"(r[1]), "=r"(r[2]), "=r"(r[3]) : "r"(a));
}
__device__ __forceinline__ void mma_f16(float* c, const uint32_t* a,
                                        uint32_t b0, uint32_t b1) {
    asm volatile(
        "mma.sync.aligned.m16n8k16.row.col.f32.f16.f16.f32 "
        "{%0,%1,%2,%3}, {%4,%5,%6,%7}, {%8,%9}, {%0,%1,%2,%3};"
        : "+f"(c[0]), "+f"(c[1]), "+f"(c[2]), "+f"(c[3])
        : "r"(a[0]), "r"(a[1]), "r"(a[2]), "r"(a[3]), "r"(b0), "r"(b1));
}

template <bool SHIFT>
__device__ __forceinline__ size_t tok_img_off(int T) {
    const int win = T >> 6, pos = T & 63;
    const int b = win >> 6, w = win & 63;
    int gr = (w >> 3) * 8 + (pos >> 3);
    int gc = (w & 7) * 8 + (pos & 7);
    if (SHIFT) { gr = (gr + 4) & 63; gc = (gc + 4) & 63; }
    return ((size_t)((b * 64 + gr) * 64 + gc)) * 256;
}
__device__ __forceinline__ int regid_of(int w, int pos) {
    const int gr = (w >> 3) * 8 + (pos >> 3);
    const int gc = (w & 7) * 8 + (pos & 7);
    const int rr = (gr < 56) ? 0 : (gr < 60 ? 1 : 2);
    const int cc = (gc < 56) ? 0 : (gc < 60 ? 1 : 2);
    return rr * 3 + cc;
}

// ---------------------------------------------------------------------------
// weight pre-pack (validated)
// ---------------------------------------------------------------------------
__global__ void prepack_w(const float* __restrict__ w, __half* __restrict__ dst,
                          int NT)
{
    const int LDB = NT * 128;
    const int total = NT * 8 * 128 * 32;
    for (int idx = blockIdx.x * blockDim.x + threadIdx.x; idx < total;
         idx += gridDim.x * blockDim.x) {
        const int k   = idx & 31;
        const int n   = (idx >> 5) & 127;
        const int blk = idx >> 12;
        const int kc  = blk & 7, nt = blk >> 3;
        const float v = w[(size_t)(kc * 32 + k) * LDB + nt * 128 + n];
        dst[(size_t)(blk * 128 + n) * HST + k] = __float2half(v);
    }
}

// ---------------------------------------------------------------------------
// fp16 mma GEMM: qkv = A[128x256] @ W + bias -> __half out. 256 thr.
// AT = float (image x) or __half (image y); A always gathered via tok_img_off.
// ---------------------------------------------------------------------------
template <int NT, typename AT, bool SHIFT>
__global__ __launch_bounds__(256, 2)
void gemm_mma(const AT* __restrict__ A, const __half* __restrict__ Bp,
              const float* __restrict__ bias, __half* __restrict__ Out)
{
    constexpr int LDB = NT * 128;
    extern __shared__ char smraw[];
    __half* As = (__half*)smraw;
    __half* Bs = (__half*)(smraw + 8 * CHUNK_H * 2);
    const uint32_t smb = smem_u32(smraw);

    const int tid  = threadIdx.x;
    const int lane = tid & 31;
    const int wid  = tid >> 5;
    const int wm   = wid & 3;
    const int wn   = wid >> 2;
    const int mt   = blockIdx.x;

    // ---- A gather + fp16 convert into 8 K-chunk smem tiles ----
    {
        const int row = tid >> 1;
        const int T   = mt * 128 + row;
        const AT* arow = A + tok_img_off<SHIFT>(T);
        if constexpr (sizeof(AT) == 4) {
#pragma unroll
            for (int j = 0; j < 32; j++) {
                const int c4  = (tid & 1) * 32 + j;          // float4 idx
                const float4 v = *((const float4*)arow + c4);
                const int col = c4 * 4;
                const int kc  = col >> 5, k = col & 31;
                uint2 u = { pack_h2(v.x, v.y), pack_h2(v.z, v.w) };
                *(uint2*)(As + (size_t)kc * CHUNK_H + row * HST + k) = u;
            }
        } else {
#pragma unroll
            for (int j = 0; j < 16; j++) {
                const int c8  = (tid & 1) * 16 + j;          // uint4 = 8 halfs
                const uint4 v = *((const uint4*)arow + c8);
                const int col = c8 * 8;
                const int kc  = col >> 5, k = col & 31;
                *(uint4*)(As + (size_t)kc * CHUNK_H + row * HST + k) = v;
            }
        }
    }

    const int a_row = (lane & 7) + ((lane >> 3) & 1) * 8;
    const int a_kb  = (lane >> 4) * 16;
    const int b_n   = (lane & 7);
    const int b_kb  = (lane >> 3) * 16;

    float acc[2][8][4];
    const int total_cc = NT * 8;

    {
#pragma unroll
        for (int j = 0; j < 3; j++) {
            const int i = tid + j * 256;
            if (i < 640) ((uint4*)Bs)[i] = ((const uint4*)Bp)[i];
        }
    }
    __syncthreads();

    for (int cc = 0; cc < total_cc; cc++) {
        const int nt  = cc >> 3;
        const int kc  = cc & 7;
        const int buf = cc & 1;

        if (kc == 0) {
#pragma unroll
            for (int mi = 0; mi < 2; mi++)
#pragma unroll
                for (int ni = 0; ni < 8; ni++)
#pragma unroll
                    for (int e = 0; e < 4; e++) acc[mi][ni][e] = 0.f;
        }

        uint4 pf[3];
        const bool more = (cc + 1 < total_cc);
        if (more) {
            const uint4* src = (const uint4*)(Bp + (size_t)(cc + 1) * CHUNK_H);
#pragma unroll
            for (int j = 0; j < 3; j++) {
                const int i = tid + j * 256;
                if (i < 640) pf[j] = src[i];
            }
        }

        const uint32_t a_base = smb + (kc * CHUNK_H + (wm * 32 + a_row) * HST) * 2 + a_kb;
        const uint32_t b_base = smb + (8 * CHUNK_H + buf * CHUNK_H
                              + (wn * 64 + b_n) * HST) * 2 + b_kb;

        uint32_t bf[8][4];
#pragma unroll
        for (int ni = 0; ni < 8; ni++)
            ldsm_x4(bf[ni], b_base + (ni * 8) * (HST * 2));
#pragma unroll
        for (int ks = 0; ks < 2; ks++) {
            uint32_t af[2][4];
#pragma unroll
            for (int mi = 0; mi < 2; mi++)
                ldsm_x4(af[mi], a_base + (mi * 16) * (HST * 2) + ks * 32);
#pragma unroll
            for (int mi = 0; mi < 2; mi++)
#pragma unroll
                for (int ni = 0; ni < 8; ni++)
                    mma_f16(acc[mi][ni], af[mi], bf[ni][2 * ks], bf[ni][2 * ks + 1]);
        }
        __syncthreads();
        if (more) {
            __half* dstb = Bs + (size_t)((cc + 1) & 1) * CHUNK_H;
#pragma unroll
            for (int j = 0; j < 3; j++) {
                const int i = tid + j * 256;
                if (i < 640) ((uint4*)dstb)[i] = pf[j];
            }
            __syncthreads();
        }

        if (kc == 7) {
            const int g  = lane >> 2, tg = lane & 3;
            const int nb = nt * 128 + wn * 64;
#pragma unroll
            for (int mi = 0; mi < 2; mi++) {
#pragma unroll
                for (int hr = 0; hr < 2; hr++) {
                    const int T = mt * 128 + wm * 32 + mi * 16 + g + hr * 8;
                    __half* orow = Out + (size_t)T * LDB;
#pragma unroll
                    for (int ni = 0; ni < 8; ni++) {
                        const int c = nb + ni * 8 + 2 * tg;
                        *(uint32_t*)(orow + c) =
                            pack_h2(acc[mi][ni][hr * 2]     + bias[c],
                                    acc[mi][ni][hr * 2 + 1] + bias[c + 1]);
                    }
                }
            }
        }
    }
}

// ---------------------------------------------------------------------------
// FUSED attention + output projection. qkv input fp16. OT = __half (pass 1,
// token->image store to g_y) or float (pass 2, final out).
// ---------------------------------------------------------------------------
template <bool MASKED, bool SHIFT, typename OT>
__global__ __launch_bounds__(256, 1)
void attn_proj(const __half* __restrict__ qkv, const __half* __restrict__ Bp,
               const float* __restrict__ bo, OT* __restrict__ Out)
{
    extern __shared__ char smraw[];
    __half* smh = (__half*)smraw;
    const int tid  = threadIdx.x;
    const int lane = tid & 31;
    const int h    = tid >> 5;
    const int win  = blockIdx.x;
    const int w    = win & 63;
    const size_t Tb = (size_t)win * 64;

    __half* qs = smh + QS_OFF + h * (16 * 40);
    __half* ks = smh + KS_OFF + h * AO_CH;
    __half* vt = smh + VT_OFF + h * (32 * 72);
    __half* pb = smh + PB_OFF + h * (16 * 72);

    const __half* hb = qkv + Tb * 768 + h * 32;

    // ---- stage K [64][32] (uint4 copy) and V^T [32][64] (scatter) ----
#pragma unroll
    for (int it = 0; it < 8; it++) {
        const int tok = it * 8 + (lane >> 2);
        const int q4  = lane & 3;                     // uint4 = 8 halfs
        const uint4 kv = *(const uint4*)(hb + (size_t)tok * 768 + 256 + q4 * 8);
        *(uint4*)(ks + tok * 40 + q4 * 8) = kv;
        const uint4 vv = *(const uint4*)(hb + (size_t)tok * 768 + 512 + q4 * 8);
        const __half* hp = (const __half*)&vv;
        const int db = q4 * 8;
#pragma unroll
        for (int e = 0; e < 8; e++)
            vt[(db + e) * 72 + tok] = hp[e];
    }

    const int g  = lane >> 2, tg = lane & 3;
    const int a_row = (lane & 7) + ((lane >> 3) & 1) * 8;
    const int a_kb  = (lane >> 4) * 16;
    const int b_n   = lane & 7;
    const int b_kb  = (lane >> 3) * 16;

    const uint32_t qs_lm = smem_u32(qs) + a_row * 80 + a_kb;
    const uint32_t pb_lm = smem_u32(pb) + a_row * 144 + a_kb;
    const uint32_t ks_lm = smem_u32(ks) + b_n * 80 + b_kb;
    const uint32_t vt_lm = smem_u32(vt) + b_n * 144 + b_kb;

    int rid_c[16];
    if (MASKED) {
#pragma unroll
        for (int ni = 0; ni < 8; ni++) {
            rid_c[ni * 2]     = regid_of(w, ni * 8 + 2 * tg);
            rid_c[ni * 2 + 1] = regid_of(w, ni * 8 + 2 * tg + 1);
        }
    }
    __syncwarp();

    float o_all[4][4][4];

    for (int mi = 0; mi < 4; mi++) {
        // ---- Q block [16][32] (uint4 copy) ----
#pragma unroll
        for (int it = 0; it < 2; it++) {
            const int row = it * 8 + (lane >> 2);
            const int q4  = lane & 3;
            const uint4 qv =
                *(const uint4*)(hb + (size_t)(mi * 16 + row) * 768 + q4 * 8);
            *(uint4*)(qs + row * 40 + q4 * 8) = qv;
        }
        __syncwarp();

        // ---- S = Q K^T ----
        float s[8][4];
#pragma unroll
        for (int ni = 0; ni < 8; ni++)
#pragma unroll
            for (int e = 0; e < 4; e++) s[ni][e] = 0.f;
        {
            uint32_t bf[8][4];
#pragma unroll
            for (int ni = 0; ni < 8; ni++)
                ldsm_x4(bf[ni], ks_lm + (ni * 8) * 80);
#pragma unroll
            for (int ksx = 0; ksx < 2; ksx++) {
                uint32_t af[4];
                ldsm_x4(af, qs_lm + ksx * 32);
#pragma unroll
                for (int ni = 0; ni < 8; ni++)
                    mma_f16(s[ni], af, bf[ni][2 * ksx], bf[ni][2 * ksx + 1]);
            }
        }

        // ---- scale + mask ----
        int r0 = 0, r1 = 0;
        if (MASKED) {
            r0 = regid_of(w, mi * 16 + g);
            r1 = regid_of(w, mi * 16 + g + 8);
        }
#pragma unroll
        for (int ni = 0; ni < 8; ni++) {
#pragma unroll
            for (int e = 0; e < 2; e++) {
                s[ni][e]     = s[ni][e] * SCALE
                             + ((MASKED && r0 != rid_c[ni * 2 + e]) ? NEGM : 0.f);
                s[ni][2 + e] = s[ni][2 + e] * SCALE
                             + ((MASKED && r1 != rid_c[ni * 2 + e]) ? NEGM : 0.f);
            }
        }

        // ---- softmax ----
        float m0 = -3.0e38f, m1 = -3.0e38f;
#pragma unroll
        for (int ni = 0; ni < 8; ni++) {
            m0 = fmaxf(m0, fmaxf(s[ni][0], s[ni][1]));
            m1 = fmaxf(m1, fmaxf(s[ni][2], s[ni][3]));
        }
        m0 = fmaxf(m0, __shfl_xor_sync(0xffffffffu, m0, 1));
        m0 = fmaxf(m0, __shfl_xor_sync(0xffffffffu, m0, 2));
        m1 = fmaxf(m1, __shfl_xor_sync(0xffffffffu, m1, 1));
        m1 = fmaxf(m1, __shfl_xor_sync(0xffffffffu, m1, 2));
        float sum0 = 0.f, sum1 = 0.f;
#pragma unroll
        for (int ni = 0; ni < 8; ni++) {
            s[ni][0] = __expf(s[ni][0] - m0); sum0 += s[ni][0];
            s[ni][1] = __expf(s[ni][1] - m0); sum0 += s[ni][1];
            s[ni][2] = __expf(s[ni][2] - m1); sum1 += s[ni][2];
            s[ni][3] = __expf(s[ni][3] - m1); sum1 += s[ni][3];
        }
        sum0 += __shfl_xor_sync(0xffffffffu, sum0, 1);
        sum0 += __shfl_xor_sync(0xffffffffu, sum0, 2);
        sum1 += __shfl_xor_sync(0xffffffffu, sum1, 1);
        sum1 += __shfl_xor_sync(0xffffffffu, sum1, 2);
        const float i0 = 1.0f / sum0, i1 = 1.0f / sum1;

        // ---- P (fp16) -> pb ----
#pragma unroll
        for (int ni = 0; ni < 8; ni++) {
            *(uint32_t*)(pb + g * 72 + ni * 8 + 2 * tg) =
                pack_h2(s[ni][0] * i0, s[ni][1] * i0);
            *(uint32_t*)(pb + (g + 8) * 72 + ni * 8 + 2 * tg) =
                pack_h2(s[ni][2] * i1, s[ni][3] * i1);
        }
        __syncwarp();

        // ---- O = P @ V ----
        float (&o)[4][4] = o_all[mi];
#pragma unroll
        for (int ni = 0; ni < 4; ni++)
#pragma unroll
            for (int e = 0; e < 4; e++) o[ni][e] = 0.f;
#pragma unroll
        for (int kp = 0; kp < 2; kp++) {
            uint32_t bf2[4][4];
#pragma unroll
            for (int ni = 0; ni < 4; ni++)
                ldsm_x4(bf2[ni], vt_lm + (ni * 8) * 144 + kp * 64);
#pragma unroll
            for (int ks2 = 0; ks2 < 2; ks2++) {
                uint32_t af[4];
                ldsm_x4(af, pb_lm + kp * 64 + ks2 * 32);
#pragma unroll
                for (int ni = 0; ni < 4; ni++)
                    mma_f16(o[ni], af, bf2[ni][2 * ks2], bf2[ni][2 * ks2 + 1]);
            }
        }
        __syncwarp();
    }

    // ---- stage ao (fp16) into dead K region ----
#pragma unroll
    for (int mi = 0; mi < 4; mi++) {
#pragma unroll
        for (int ni = 0; ni < 4; ni++) {
            const int c = ni * 8 + 2 * tg;
            *(uint32_t*)(ks + (mi * 16 + g) * 40 + c) =
                pack_h2(o_all[mi][ni][0], o_all[mi][ni][1]);
            *(uint32_t*)(ks + (mi * 16 + g + 8) * 40 + c) =
                pack_h2(o_all[mi][ni][2], o_all[mi][ni][3]);
        }
    }
    __syncthreads();

    // ================= phase 2: out = ao @ Wo + bo =================
    const uint32_t ao_base = smem_u32(smh) + KS_OFF * 2;
    __half* Bs = smh + VT_OFF;

    const int wm = (tid >> 5) & 1;
    const int wn = (tid >> 5) >> 1;

    {
#pragma unroll
        for (int j = 0; j < 3; j++) {
            const int i = tid + j * 256;
            if (i < 640) ((uint4*)Bs)[i] = ((const uint4*)Bp)[i];
        }
    }
    __syncthreads();

    float acc[2][4][4];
    for (int cc = 0; cc < 16; cc++) {
        const int nt  = cc >> 3;
        const int kc  = cc & 7;
        const int buf = cc & 1;

        if (kc == 0) {
#pragma unroll
            for (int mi = 0; mi < 2; mi++)
#pragma unroll
                for (int ni = 0; ni < 4; ni++)
#pragma unroll
                    for (int e = 0; e < 4; e++) acc[mi][ni][e] = 0.f;
        }

        uint4 pf[3];
        const bool more = (cc + 1 < 16);
        if (more) {
            const uint4* src = (const uint4*)(Bp + (size_t)(cc + 1) * CHUNK_H);
#pragma unroll
            for (int j = 0; j < 3; j++) {
                const int i = tid + j * 256;
                if (i < 640) pf[j] = src[i];
            }
        }

        const uint32_t a_base = ao_base + (kc * AO_CH + (wm * 32 + a_row) * 40) * 2 + a_kb;
        const uint32_t b_base = smem_u32(Bs) + (buf * CHUNK_H + (wn * 32 + b_n) * 40) * 2 + b_kb;

        uint32_t bf[4][4];
#pragma unroll
        for (int ni = 0; ni < 4; ni++)
            ldsm_x4(bf[ni], b_base + (ni * 8) * 80);
#pragma unroll
        for (int ksx = 0; ksx < 2; ksx++) {
            uint32_t af[2][4];
#pragma unroll
            for (int mi = 0; mi < 2; mi++)
                ldsm_x4(af[mi], a_base + (mi * 16) * 80 + ksx * 32);
#pragma unroll
            for (int mi = 0; mi < 2; mi++)
#pragma unroll
                for (int ni = 0; ni < 4; ni++)
                    mma_f16(acc[mi][ni], af[mi], bf[ni][2 * ksx], bf[ni][2 * ksx + 1]);
        }
        __syncthreads();
        if (more) {
            __half* dstb = Bs + (size_t)((cc + 1) & 1) * CHUNK_H;
#pragma unroll
            for (int j = 0; j < 3; j++) {
                const int i = tid + j * 256;
                if (i < 640) ((uint4*)dstb)[i] = pf[j];
            }
            __syncthreads();
        }

        if (kc == 7) {
            const int nb = nt * 128 + wn * 32;
#pragma unroll
            for (int mi = 0; mi < 2; mi++) {
#pragma unroll
                for (int hr = 0; hr < 2; hr++) {
                    const int row = wm * 32 + mi * 16 + g + hr * 8;
                    OT* orow = Out + tok_img_off<SHIFT>((int)(Tb + row));
#pragma unroll
                    for (int ni = 0; ni < 4; ni++) {
                        const int c = nb + ni * 8 + 2 * tg;
                        const float v0 = acc[mi][ni][hr * 2]     + bo[c];
                        const float v1 = acc[mi][ni][hr * 2 + 1] + bo[c + 1];
                        if constexpr (sizeof(OT) == 4) {
                            *(float2*)((float*)orow + c) = make_float2(v0, v1);
                        } else {
                            *(uint32_t*)((__half*)orow + c) = pack_h2(v0, v1);
                        }
                    }
                }
            }
        }
    }
}

// ---------------------------------------------------------------------------
extern "C" void kernel_launch(void* const* d_in, const int* in_sizes, int n_in,
                              void* d_out, int out_size)
{
    const float* x    = (const float*)d_in[0];
    const float* wqkv = (const float*)d_in[1];
    const float* bqkv = (const float*)d_in[2];
    const float* wo   = (const float*)d_in[3];
    const float* bo   = (const float*)d_in[4];
    float* out = (float*)d_out;

    __half *qkv_p, *y_p, *wq_p, *wo_pk;
    cudaGetSymbolAddress((void**)&qkv_p, g_qkv);
    cudaGetSymbolAddress((void**)&y_p,   g_y);
    cudaGetSymbolAddress((void**)&wq_p,  g_wqkv_h);
    cudaGetSymbolAddress((void**)&wo_pk, g_wo_h);

    cudaFuncSetAttribute(gemm_mma<6, float, false>,
                         cudaFuncAttributeMaxDynamicSharedMemorySize, GSMEM);
    cudaFuncSetAttribute(gemm_mma<6, __half, true>,
                         cudaFuncAttributeMaxDynamicSharedMemorySize, GSMEM);
    cudaFuncSetAttribute(attn_proj<false, false, __half>,
                         cudaFuncAttributeMaxDynamicSharedMemorySize, ASMEM);
    cudaFuncSetAttribute(attn_proj<true, true, float>,
                         cudaFuncAttributeMaxDynamicSharedMemorySize, ASMEM);

    prepack_w<<<192, 256>>>(wqkv, wq_p, 6);
    prepack_w<<<64,  256>>>(wo,   wo_pk, 2);

    // pass 1 (unshifted): x (fp32 image) -> qkv (fp16) -> y (fp16 image)
    gemm_mma<6, float, false><<<MT, 256, GSMEM>>>(x, wq_p, bqkv, qkv_p);
    attn_proj<false, false, __half><<<2048, 256, ASMEM>>>(qkv_p, wo_pk, bo, y_p);
    // pass 2 (shifted+mask): y (fp16 image, roll) -> qkv -> out (fp32, inv roll)
    gemm_mma<6, __half, true><<<MT, 256, GSMEM>>>(y_p, wq_p, bqkv, qkv_p);
    attn_proj<true, true, float><<<2048, 256, ASMEM>>>(qkv_p, wo_pk, bo, out);
}

// round 15
// speedup vs baseline: 2.4191x; 1.0582x over previous
#include <cuda_runtime.h>
#include <cuda_fp16.h>
#include <cstdint>

// ===========================================================================
// SWIN attention layer on GB300 (sm_103 base target — NO tcgen05).
// R15: fp16 mma everywhere, fp16 intermediates, attn_proj at 2 CTAs/SM
// (O packed to fp16 right after PV -> regs<=128).
// ===========================================================================

namespace {
constexpr int TOK = 32 * 64 * 64;          // 131072 tokens
constexpr int MT  = TOK / 128;             // 1024 M-tiles
constexpr float SCALE = 0.17677669529663687f;
constexpr float NEGM  = -1e9f;
constexpr int HST = 40;                    // smem row stride (halfs)
constexpr int CHUNK_H = 128 * HST;         // 5120 halfs per [128][32] tile
constexpr int GSMEM = (8 * CHUNK_H + 2 * CHUNK_H) * 2;   // 102400 B

// fused attn+proj smem layout (halfs)
constexpr int QS_OFF = 0;                          // [8][16][40]  Q staging
constexpr int KS_OFF = QS_OFF + 8 * 16 * 40;       // [8][64][40]  K, then ao
constexpr int VT_OFF = KS_OFF + 8 * 64 * 40;       // [8][32][72]  V^T, then Wo
constexpr int PB_OFF = VT_OFF + 8 * 32 * 72;       // [8][16][72]  P staging
constexpr int ASMEM  = (PB_OFF + 8 * 16 * 72) * 2; // 106496 B
constexpr int AO_CH  = 64 * HST;
}

// static device scratch (fp16 intermediates)
__device__ __half g_qkv[(size_t)TOK * 768];
__device__ __half g_y  [(size_t)TOK * 256];
__device__ __half g_wqkv_h[6 * 8 * 128 * HST];
__device__ __half g_wo_h  [2 * 8 * 128 * HST];

__device__ __forceinline__ uint32_t smem_u32(const void* p) {
    uint32_t a;
    asm("{ .reg .u64 t; cvta.to.shared.u64 t, %1; cvt.u32.u64 %0, t; }"
        : "=r"(a) : "l"(p));
    return a;
}
__device__ __forceinline__ uint32_t pack_h2(float a, float b) {
    __half2 h = __floats2half2_rn(a, b);
    return *(uint32_t*)&h;
}
__device__ __forceinline__ void ldsm_x4(uint32_t* r, uint32_t a) {
    asm volatile("ldmatrix.sync.aligned.m8n8.x4.shared.b16 {%0,%1,%2,%3}, [%4];"
                 : "=r"(r[0]), "=r"(r[1]), "=r"(r[2]), "=r"(r[3]) : "r"(a));
}
__device__ __forceinline__ void mma_f16(float* c, const uint32_t* a,
                                        uint32_t b0, uint32_t b1) {
    asm volatile(
        "mma.sync.aligned.m16n8k16.row.col.f32.f16.f16.f32 "
        "{%0,%1,%2,%3}, {%4,%5,%6,%7}, {%8,%9}, {%0,%1,%2,%3};"
        : "+f"(c[0]), "+f"(c[1]), "+f"(c[2]), "+f"(c[3])
        : "r"(a[0]), "r"(a[1]), "r"(a[2]), "r"(a[3]), "r"(b0), "r"(b1));
}

template <bool SHIFT>
__device__ __forceinline__ size_t tok_img_off(int T) {
    const int win = T >> 6, pos = T & 63;
    const int b = win >> 6, w = win & 63;
    int gr = (w >> 3) * 8 + (pos >> 3);
    int gc = (w & 7) * 8 + (pos & 7);
    if (SHIFT) { gr = (gr + 4) & 63; gc = (gc + 4) & 63; }
    return ((size_t)((b * 64 + gr) * 64 + gc)) * 256;
}
__device__ __forceinline__ int regid_of(int w, int pos) {
    const int gr = (w >> 3) * 8 + (pos >> 3);
    const int gc = (w & 7) * 8 + (pos & 7);
    const int rr = (gr < 56) ? 0 : (gr < 60 ? 1 : 2);
    const int cc = (gc < 56) ? 0 : (gc < 60 ? 1 : 2);
    return rr * 3 + cc;
}

// ---------------------------------------------------------------------------
// weight pre-pack (validated)
// ---------------------------------------------------------------------------
__global__ void prepack_w(const float* __restrict__ w, __half* __restrict__ dst,
                          int NT)
{
    const int LDB = NT * 128;
    const int total = NT * 8 * 128 * 32;
    for (int idx = blockIdx.x * blockDim.x + threadIdx.x; idx < total;
         idx += gridDim.x * blockDim.x) {
        const int k   = idx & 31;
        const int n   = (idx >> 5) & 127;
        const int blk = idx >> 12;
        const int kc  = blk & 7, nt = blk >> 3;
        const float v = w[(size_t)(kc * 32 + k) * LDB + nt * 128 + n];
        dst[(size_t)(blk * 128 + n) * HST + k] = __float2half(v);
    }
}

// ---------------------------------------------------------------------------
// fp16 mma GEMM: qkv = A[128x256] @ W + bias -> __half out. 256 thr, 2 CTAs/SM.
// ---------------------------------------------------------------------------
template <int NT, typename AT, bool SHIFT>
__global__ __launch_bounds__(256, 2)
void gemm_mma(const AT* __restrict__ A, const __half* __restrict__ Bp,
              const float* __restrict__ bias, __half* __restrict__ Out)
{
    constexpr int LDB = NT * 128;
    extern __shared__ char smraw[];
    __half* As = (__half*)smraw;
    __half* Bs = (__half*)(smraw + 8 * CHUNK_H * 2);
    const uint32_t smb = smem_u32(smraw);

    const int tid  = threadIdx.x;
    const int lane = tid & 31;
    const int wid  = tid >> 5;
    const int wm   = wid & 3;
    const int wn   = wid >> 2;
    const int mt   = blockIdx.x;

    // ---- A gather + fp16 convert into 8 K-chunk smem tiles ----
    {
        const int row = tid >> 1;
        const int T   = mt * 128 + row;
        const AT* arow = A + tok_img_off<SHIFT>(T);
        if constexpr (sizeof(AT) == 4) {
#pragma unroll
            for (int j = 0; j < 32; j++) {
                const int c4  = (tid & 1) * 32 + j;
                const float4 v = *((const float4*)arow + c4);
                const int col = c4 * 4;
                const int kc  = col >> 5, k = col & 31;
                uint2 u = { pack_h2(v.x, v.y), pack_h2(v.z, v.w) };
                *(uint2*)(As + (size_t)kc * CHUNK_H + row * HST + k) = u;
            }
        } else {
#pragma unroll
            for (int j = 0; j < 16; j++) {
                const int c8  = (tid & 1) * 16 + j;
                const uint4 v = *((const uint4*)arow + c8);
                const int col = c8 * 8;
                const int kc  = col >> 5, k = col & 31;
                *(uint4*)(As + (size_t)kc * CHUNK_H + row * HST + k) = v;
            }
        }
    }

    const int a_row = (lane & 7) + ((lane >> 3) & 1) * 8;
    const int a_kb  = (lane >> 4) * 16;
    const int b_n   = (lane & 7);
    const int b_kb  = (lane >> 3) * 16;

    float acc[2][8][4];
    const int total_cc = NT * 8;

    {
#pragma unroll
        for (int j = 0; j < 3; j++) {
            const int i = tid + j * 256;
            if (i < 640) ((uint4*)Bs)[i] = ((const uint4*)Bp)[i];
        }
    }
    __syncthreads();

    for (int cc = 0; cc < total_cc; cc++) {
        const int nt  = cc >> 3;
        const int kc  = cc & 7;
        const int buf = cc & 1;

        if (kc == 0) {
#pragma unroll
            for (int mi = 0; mi < 2; mi++)
#pragma unroll
                for (int ni = 0; ni < 8; ni++)
#pragma unroll
                    for (int e = 0; e < 4; e++) acc[mi][ni][e] = 0.f;
        }

        uint4 pf[3];
        const bool more = (cc + 1 < total_cc);
        if (more) {
            const uint4* src = (const uint4*)(Bp + (size_t)(cc + 1) * CHUNK_H);
#pragma unroll
            for (int j = 0; j < 3; j++) {
                const int i = tid + j * 256;
                if (i < 640) pf[j] = src[i];
            }
        }

        const uint32_t a_base = smb + (kc * CHUNK_H + (wm * 32 + a_row) * HST) * 2 + a_kb;
        const uint32_t b_base = smb + (8 * CHUNK_H + buf * CHUNK_H
                              + (wn * 64 + b_n) * HST) * 2 + b_kb;

        uint32_t bf[8][4];
#pragma unroll
        for (int ni = 0; ni < 8; ni++)
            ldsm_x4(bf[ni], b_base + (ni * 8) * (HST * 2));
#pragma unroll
        for (int ks = 0; ks < 2; ks++) {
            uint32_t af[2][4];
#pragma unroll
            for (int mi = 0; mi < 2; mi++)
                ldsm_x4(af[mi], a_base + (mi * 16) * (HST * 2) + ks * 32);
#pragma unroll
            for (int mi = 0; mi < 2; mi++)
#pragma unroll
                for (int ni = 0; ni < 8; ni++)
                    mma_f16(acc[mi][ni], af[mi], bf[ni][2 * ks], bf[ni][2 * ks + 1]);
        }
        __syncthreads();
        if (more) {
            __half* dstb = Bs + (size_t)((cc + 1) & 1) * CHUNK_H;
#pragma unroll
            for (int j = 0; j < 3; j++) {
                const int i = tid + j * 256;
                if (i < 640) ((uint4*)dstb)[i] = pf[j];
            }
            __syncthreads();
        }

        if (kc == 7) {
            const int g  = lane >> 2, tg = lane & 3;
            const int nb = nt * 128 + wn * 64;
#pragma unroll
            for (int mi = 0; mi < 2; mi++) {
#pragma unroll
                for (int hr = 0; hr < 2; hr++) {
                    const int T = mt * 128 + wm * 32 + mi * 16 + g + hr * 8;
                    __half* orow = Out + (size_t)T * LDB;
#pragma unroll
                    for (int ni = 0; ni < 8; ni++) {
                        const int c = nb + ni * 8 + 2 * tg;
                        *(uint32_t*)(orow + c) =
                            pack_h2(acc[mi][ni][hr * 2]     + bias[c],
                                    acc[mi][ni][hr * 2 + 1] + bias[c + 1]);
                    }
                }
            }
        }
    }
}

// ---------------------------------------------------------------------------
// FUSED attention + output projection, 2 CTAs/SM (O packed fp16 after PV).
// ---------------------------------------------------------------------------
template <bool MASKED, bool SHIFT, typename OT>
__global__ __launch_bounds__(256, 2)
void attn_proj(const __half* __restrict__ qkv, const __half* __restrict__ Bp,
               const float* __restrict__ bo, OT* __restrict__ Out)
{
    extern __shared__ char smraw[];
    __half* smh = (__half*)smraw;
    const int tid  = threadIdx.x;
    const int lane = tid & 31;
    const int h    = tid >> 5;
    const int win  = blockIdx.x;
    const int w    = win & 63;
    const size_t Tb = (size_t)win * 64;

    __half* qs = smh + QS_OFF + h * (16 * 40);
    __half* ks = smh + KS_OFF + h * AO_CH;
    __half* vt = smh + VT_OFF + h * (32 * 72);
    __half* pb = smh + PB_OFF + h * (16 * 72);

    const __half* hb = qkv + Tb * 768 + h * 32;

    // ---- stage K [64][32] (uint4 copy) and V^T [32][64] (scatter) ----
#pragma unroll
    for (int it = 0; it < 8; it++) {
        const int tok = it * 8 + (lane >> 2);
        const int q4  = lane & 3;
        const uint4 kv = *(const uint4*)(hb + (size_t)tok * 768 + 256 + q4 * 8);
        *(uint4*)(ks + tok * 40 + q4 * 8) = kv;
        const uint4 vv = *(const uint4*)(hb + (size_t)tok * 768 + 512 + q4 * 8);
        const __half* hp = (const __half*)&vv;
        const int db = q4 * 8;
#pragma unroll
        for (int e = 0; e < 8; e++)
            vt[(db + e) * 72 + tok] = hp[e];
    }

    const int g  = lane >> 2, tg = lane & 3;
    const int a_row = (lane & 7) + ((lane >> 3) & 1) * 8;
    const int a_kb  = (lane >> 4) * 16;
    const int b_n   = lane & 7;
    const int b_kb  = (lane >> 3) * 16;

    const uint32_t qs_lm = smem_u32(qs) + a_row * 80 + a_kb;
    const uint32_t pb_lm = smem_u32(pb) + a_row * 144 + a_kb;
    const uint32_t ks_lm = smem_u32(ks) + b_n * 80 + b_kb;
    const uint32_t vt_lm = smem_u32(vt) + b_n * 144 + b_kb;

    int rid_c[16];
    if (MASKED) {
#pragma unroll
        for (int ni = 0; ni < 8; ni++) {
            rid_c[ni * 2]     = regid_of(w, ni * 8 + 2 * tg);
            rid_c[ni * 2 + 1] = regid_of(w, ni * 8 + 2 * tg + 1);
        }
    }
    __syncwarp();

    uint32_t o_pk[4][4][2];   // O for all 4 q-blocks, packed fp16 (32 regs)

    for (int mi = 0; mi < 4; mi++) {
        // ---- Q block [16][32] (uint4 copy) ----
#pragma unroll
        for (int it = 0; it < 2; it++) {
            const int row = it * 8 + (lane >> 2);
            const int q4  = lane & 3;
            const uint4 qv =
                *(const uint4*)(hb + (size_t)(mi * 16 + row) * 768 + q4 * 8);
            *(uint4*)(qs + row * 40 + q4 * 8) = qv;
        }
        __syncwarp();

        // ---- S = Q K^T ----
        float s[8][4];
#pragma unroll
        for (int ni = 0; ni < 8; ni++)
#pragma unroll
            for (int e = 0; e < 4; e++) s[ni][e] = 0.f;
        {
            uint32_t bf[8][4];
#pragma unroll
            for (int ni = 0; ni < 8; ni++)
                ldsm_x4(bf[ni], ks_lm + (ni * 8) * 80);
#pragma unroll
            for (int ksx = 0; ksx < 2; ksx++) {
                uint32_t af[4];
                ldsm_x4(af, qs_lm + ksx * 32);
#pragma unroll
                for (int ni = 0; ni < 8; ni++)
                    mma_f16(s[ni], af, bf[ni][2 * ksx], bf[ni][2 * ksx + 1]);
            }
        }

        // ---- scale + mask ----
        int r0 = 0, r1 = 0;
        if (MASKED) {
            r0 = regid_of(w, mi * 16 + g);
            r1 = regid_of(w, mi * 16 + g + 8);
        }
#pragma unroll
        for (int ni = 0; ni < 8; ni++) {
#pragma unroll
            for (int e = 0; e < 2; e++) {
                s[ni][e]     = s[ni][e] * SCALE
                             + ((MASKED && r0 != rid_c[ni * 2 + e]) ? NEGM : 0.f);
                s[ni][2 + e] = s[ni][2 + e] * SCALE
                             + ((MASKED && r1 != rid_c[ni * 2 + e]) ? NEGM : 0.f);
            }
        }

        // ---- softmax ----
        float m0 = -3.0e38f, m1 = -3.0e38f;
#pragma unroll
        for (int ni = 0; ni < 8; ni++) {
            m0 = fmaxf(m0, fmaxf(s[ni][0], s[ni][1]));
            m1 = fmaxf(m1, fmaxf(s[ni][2], s[ni][3]));
        }
        m0 = fmaxf(m0, __shfl_xor_sync(0xffffffffu, m0, 1));
        m0 = fmaxf(m0, __shfl_xor_sync(0xffffffffu, m0, 2));
        m1 = fmaxf(m1, __shfl_xor_sync(0xffffffffu, m1, 1));
        m1 = fmaxf(m1, __shfl_xor_sync(0xffffffffu, m1, 2));
        float sum0 = 0.f, sum1 = 0.f;
#pragma unroll
        for (int ni = 0; ni < 8; ni++) {
            s[ni][0] = __expf(s[ni][0] - m0); sum0 += s[ni][0];
            s[ni][1] = __expf(s[ni][1] - m0); sum0 += s[ni][1];
            s[ni][2] = __expf(s[ni][2] - m1); sum1 += s[ni][2];
            s[ni][3] = __expf(s[ni][3] - m1); sum1 += s[ni][3];
        }
        sum0 += __shfl_xor_sync(0xffffffffu, sum0, 1);
        sum0 += __shfl_xor_sync(0xffffffffu, sum0, 2);
        sum1 += __shfl_xor_sync(0xffffffffu, sum1, 1);
        sum1 += __shfl_xor_sync(0xffffffffu, sum1, 2);
        const float i0 = 1.0f / sum0, i1 = 1.0f / sum1;

        // ---- P (fp16) -> pb ----
#pragma unroll
        for (int ni = 0; ni < 8; ni++) {
            *(uint32_t*)(pb + g * 72 + ni * 8 + 2 * tg) =
                pack_h2(s[ni][0] * i0, s[ni][1] * i0);
            *(uint32_t*)(pb + (g + 8) * 72 + ni * 8 + 2 * tg) =
                pack_h2(s[ni][2] * i1, s[ni][3] * i1);
        }
        __syncwarp();

        // ---- O = P @ V, pack fp16 immediately ----
        float o[4][4];
#pragma unroll
        for (int ni = 0; ni < 4; ni++)
#pragma unroll
            for (int e = 0; e < 4; e++) o[ni][e] = 0.f;
#pragma unroll
        for (int kp = 0; kp < 2; kp++) {
            uint32_t bf2[4][4];
#pragma unroll
            for (int ni = 0; ni < 4; ni++)
                ldsm_x4(bf2[ni], vt_lm + (ni * 8) * 144 + kp * 64);
#pragma unroll
            for (int ks2 = 0; ks2 < 2; ks2++) {
                uint32_t af[4];
                ldsm_x4(af, pb_lm + kp * 64 + ks2 * 32);
#pragma unroll
                for (int ni = 0; ni < 4; ni++)
                    mma_f16(o[ni], af, bf2[ni][2 * ks2], bf2[ni][2 * ks2 + 1]);
            }
        }
#pragma unroll
        for (int ni = 0; ni < 4; ni++) {
            o_pk[mi][ni][0] = pack_h2(o[ni][0], o[ni][1]);
            o_pk[mi][ni][1] = pack_h2(o[ni][2], o[ni][3]);
        }
        __syncwarp();
    }

    // ---- stage ao (fp16) into dead K region ----
#pragma unroll
    for (int mi = 0; mi < 4; mi++) {
#pragma unroll
        for (int ni = 0; ni < 4; ni++) {
            const int c = ni * 8 + 2 * tg;
            *(uint32_t*)(ks + (mi * 16 + g) * 40 + c)     = o_pk[mi][ni][0];
            *(uint32_t*)(ks + (mi * 16 + g + 8) * 40 + c) = o_pk[mi][ni][1];
        }
    }
    __syncthreads();

    // ================= phase 2: out = ao @ Wo + bo =================
    const uint32_t ao_base = smem_u32(smh) + KS_OFF * 2;
    __half* Bs = smh + VT_OFF;

    const int wm = (tid >> 5) & 1;
    const int wn = (tid >> 5) >> 1;

    {
#pragma unroll
        for (int j = 0; j < 3; j++) {
            const int i = tid + j * 256;
            if (i < 640) ((uint4*)Bs)[i] = ((const uint4*)Bp)[i];
        }
    }
    __syncthreads();

    float acc[2][4][4];
    for (int cc = 0; cc < 16; cc++) {
        const int nt  = cc >> 3;
        const int kc  = cc & 7;
        const int buf = cc & 1;

        if (kc == 0) {
#pragma unroll
            for (int mi = 0; mi < 2; mi++)
#pragma unroll
                for (int ni = 0; ni < 4; ni++)
#pragma unroll
                    for (int e = 0; e < 4; e++) acc[mi][ni][e] = 0.f;
        }

        uint4 pf[3];
        const bool more = (cc + 1 < 16);
        if (more) {
            const uint4* src = (const uint4*)(Bp + (size_t)(cc + 1) * CHUNK_H);
#pragma unroll
            for (int j = 0; j < 3; j++) {
                const int i = tid + j * 256;
                if (i < 640) pf[j] = src[i];
            }
        }

        const uint32_t a_base = ao_base + (kc * AO_CH + (wm * 32 + a_row) * 40) * 2 + a_kb;
        const uint32_t b_base = smem_u32(Bs) + (buf * CHUNK_H + (wn * 32 + b_n) * 40) * 2 + b_kb;

        uint32_t bf[4][4];
#pragma unroll
        for (int ni = 0; ni < 4; ni++)
            ldsm_x4(bf[ni], b_base + (ni * 8) * 80);
#pragma unroll
        for (int ksx = 0; ksx < 2; ksx++) {
            uint32_t af[2][4];
#pragma unroll
            for (int mi = 0; mi < 2; mi++)
                ldsm_x4(af[mi], a_base + (mi * 16) * 80 + ksx * 32);
#pragma unroll
            for (int mi = 0; mi < 2; mi++)
#pragma unroll
                for (int ni = 0; ni < 4; ni++)
                    mma_f16(acc[mi][ni], af[mi], bf[ni][2 * ksx], bf[ni][2 * ksx + 1]);
        }
        __syncthreads();
        if (more) {
            __half* dstb = Bs + (size_t)((cc + 1) & 1) * CHUNK_H;
#pragma unroll
            for (int j = 0; j < 3; j++) {
                const int i = tid + j * 256;
                if (i < 640) ((uint4*)dstb)[i] = pf[j];
            }
            __syncthreads();
        }

        if (kc == 7) {
            const int nb = nt * 128 + wn * 32;
#pragma unroll
            for (int mi = 0; mi < 2; mi++) {
#pragma unroll
                for (int hr = 0; hr < 2; hr++) {
                    const int row = wm * 32 + mi * 16 + g + hr * 8;
                    OT* orow = Out + tok_img_off<SHIFT>((int)(Tb + row));
#pragma unroll
                    for (int ni = 0; ni < 4; ni++) {
                        const int c = nb + ni * 8 + 2 * tg;
                        const float v0 = acc[mi][ni][hr * 2]     + bo[c];
                        const float v1 = acc[mi][ni][hr * 2 + 1] + bo[c + 1];
                        if constexpr (sizeof(OT) == 4) {
                            *(float2*)((float*)orow + c) = make_float2(v0, v1);
                        } else {
                            *(uint32_t*)((__half*)orow + c) = pack_h2(v0, v1);
                        }
                    }
                }
            }
        }
    }
}

// ---------------------------------------------------------------------------
extern "C" void kernel_launch(void* const* d_in, const int* in_sizes, int n_in,
                              void* d_out, int out_size)
{
    const float* x    = (const float*)d_in[0];
    const float* wqkv = (const float*)d_in[1];
    const float* bqkv = (const float*)d_in[2];
    const float* wo   = (const float*)d_in[3];
    const float* bo   = (const float*)d_in[4];
    float* out = (float*)d_out;

    __half *qkv_p, *y_p, *wq_p, *wo_pk;
    cudaGetSymbolAddress((void**)&qkv_p, g_qkv);
    cudaGetSymbolAddress((void**)&y_p,   g_y);
    cudaGetSymbolAddress((void**)&wq_p,  g_wqkv_h);
    cudaGetSymbolAddress((void**)&wo_pk, g_wo_h);

    cudaFuncSetAttribute(gemm_mma<6, float, false>,
                         cudaFuncAttributeMaxDynamicSharedMemorySize, GSMEM);
    cudaFuncSetAttribute(gemm_mma<6, __half, true>,
                         cudaFuncAttributeMaxDynamicSharedMemorySize, GSMEM);
    cudaFuncSetAttribute(attn_proj<false, false, __half>,
                         cudaFuncAttributeMaxDynamicSharedMemorySize, ASMEM);
    cudaFuncSetAttribute(attn_proj<true, true, float>,
                         cudaFuncAttributeMaxDynamicSharedMemorySize, ASMEM);

    prepack_w<<<192, 256>>>(wqkv, wq_p, 6);
    prepack_w<<<64,  256>>>(wo,   wo_pk, 2);

    // pass 1 (unshifted): x (fp32 image) -> qkv (fp16) -> y (fp16 image)
    gemm_mma<6, float, false><<<MT, 256, GSMEM>>>(x, wq_p, bqkv, qkv_p);
    attn_proj<false, false, __half><<<2048, 256, ASMEM>>>(qkv_p, wo_pk, bo, y_p);
    // pass 2 (shifted+mask): y (fp16 image, roll) -> qkv -> out (fp32, inv roll)
    gemm_mma<6, __half, true><<<MT, 256, GSMEM>>>(y_p, wq_p, bqkv, qkv_p);
    attn_proj<true, true, float><<<2048, 256, ASMEM>>>(qkv_p, wo_pk, bo, out);
}